// round 1
// baseline (speedup 1.0000x reference)
#include <cuda_runtime.h>
#include <math.h>

#define DIM     2048
#define TWO_DIM 4096
#define NH      16
#define HD      128
#define BATCH   4
#define SEQT    2048
#define M_TOK   8192   // BATCH*SEQT

// Scratch (allocation-free rule: __device__ globals)
__device__ float g_KV[(size_t)M_TOK * TWO_DIM];  // 134 MB  (K | V concatenated on cols)
__device__ float g_Q [(size_t)M_TOK * DIM];      // 67 MB
__device__ float g_O [(size_t)M_TOK * DIM];      // 67 MB

// ---------------------------------------------------------------------------
// C[M,N] = A[M,K] @ B[K,N] + bias[N]   (fp32, 128x128x16 tiles, 8x8/thread)
// ---------------------------------------------------------------------------
__global__ __launch_bounds__(256)
void gemm_bias_kernel(const float* __restrict__ A, const float* __restrict__ Bm,
                      const float* __restrict__ bias, float* __restrict__ C,
                      int M, int N, int K) {
    const int BM = 128, BN = 128, BK = 16;
    __shared__ float As[128][17];   // +1 pad: rows 1 apart -> distinct banks
    __shared__ float Bs[16][128];

    int tid = threadIdx.x;
    int tx = tid & 15;
    int ty = tid >> 4;
    int row0 = blockIdx.y * BM;
    int col0 = blockIdx.x * BN;

    float acc[8][8];
    #pragma unroll
    for (int i = 0; i < 8; i++)
        #pragma unroll
        for (int j = 0; j < 8; j++) acc[i][j] = 0.f;

    for (int kt = 0; kt < K; kt += BK) {
        // Load A tile: 128x16
        #pragma unroll
        for (int idx = tid; idx < BM * BK; idx += 256) {
            int r = idx >> 4, c = idx & 15;
            As[r][c] = A[(size_t)(row0 + r) * K + kt + c];
        }
        // Load B tile: 16x128 (fully coalesced)
        #pragma unroll
        for (int idx = tid; idx < BK * BN; idx += 256) {
            int r = idx >> 7, c = idx & 127;
            Bs[r][c] = Bm[(size_t)(kt + r) * N + col0 + c];
        }
        __syncthreads();

        #pragma unroll
        for (int kk = 0; kk < BK; kk++) {
            float a[8], b[8];
            #pragma unroll
            for (int i = 0; i < 8; i++) a[i] = As[ty + i * 16][kk];
            #pragma unroll
            for (int j = 0; j < 8; j++) b[j] = Bs[kk][tx + j * 16];
            #pragma unroll
            for (int i = 0; i < 8; i++)
                #pragma unroll
                for (int j = 0; j < 8; j++)
                    acc[i][j] = fmaf(a[i], b[j], acc[i][j]);
        }
        __syncthreads();
    }

    #pragma unroll
    for (int j = 0; j < 8; j++) {
        float bb = bias[col0 + tx + j * 16];
        #pragma unroll
        for (int i = 0; i < 8; i++) {
            C[(size_t)(row0 + ty + i * 16) * N + col0 + tx + j * 16] = acc[i][j] + bb;
        }
    }
}

// ---------------------------------------------------------------------------
// Causal flash attention, fp32. Tiles: 64 q-rows x 64 k-cols, head dim 128.
// Grid: (T/64, NH, BATCH), block 256 threads.
// Q layout: [8192, 2048] (col = h*128+d).  K,V inside g_KV: cols [0:2048),[2048:4096)
// ---------------------------------------------------------------------------
#define BMQ 64
#define BNK 64

__global__ __launch_bounds__(256)
void attn_kernel(const float* __restrict__ Q, const float* __restrict__ KV,
                 float* __restrict__ O) {
    extern __shared__ float sm[];
    float* Qs  = sm;                  // 64*129
    float* Ks  = Qs + 64 * 129;       // 64*129
    float* Vs  = Ks + 64 * 129;       // 64*129
    float* Ps  = Vs + 64 * 129;       // 64*65
    float* m_s = Ps + 64 * 65;        // 64
    float* l_s = m_s + 64;            // 64
    float* a_s = l_s + 64;            // 64

    int tid = threadIdx.x;
    int tx = tid & 15;
    int ty = tid >> 4;
    int qb = blockIdx.x, h = blockIdx.y, b = blockIdx.z;
    int q0 = qb * BMQ;
    const float scale = 0.08838834764831845f;   // 1/sqrt(128)

    // Load Q tile (64x128), coalesced over d
    for (int idx = tid; idx < BMQ * HD; idx += 256) {
        int r = idx >> 7, c = idx & 127;
        Qs[r * 129 + c] = Q[(size_t)(b * SEQT + q0 + r) * DIM + h * HD + c];
    }
    if (tid < 64) { m_s[tid] = -1e30f; l_s[tid] = 0.f; }

    float acc[4][8];
    #pragma unroll
    for (int i = 0; i < 4; i++)
        #pragma unroll
        for (int j = 0; j < 8; j++) acc[i][j] = 0.f;

    int nkb = qb + 1;   // causal: only blocks with kb <= qb
    for (int kb = 0; kb < nkb; kb++) {
        __syncthreads();   // Q/prev-KV consumers done before overwrite
        for (int idx = tid; idx < BNK * HD; idx += 256) {
            int r = idx >> 7, c = idx & 127;
            size_t base = (size_t)(b * SEQT + kb * BNK + r) * TWO_DIM + h * HD + c;
            Ks[r * 129 + c] = KV[base];
            Vs[r * 129 + c] = KV[base + DIM];
        }
        __syncthreads();

        // S = Q @ K^T   (each thread: 4x4 of the 64x64 tile)
        float s[4][4];
        #pragma unroll
        for (int i = 0; i < 4; i++)
            #pragma unroll
            for (int j = 0; j < 4; j++) s[i][j] = 0.f;

        #pragma unroll 4
        for (int d = 0; d < HD; d++) {
            float a[4], bk[4];
            #pragma unroll
            for (int i = 0; i < 4; i++) a[i]  = Qs[(ty + i * 16) * 129 + d];
            #pragma unroll
            for (int j = 0; j < 4; j++) bk[j] = Ks[(tx + j * 16) * 129 + d];
            #pragma unroll
            for (int i = 0; i < 4; i++)
                #pragma unroll
                for (int j = 0; j < 4; j++)
                    s[i][j] = fmaf(a[i], bk[j], s[i][j]);
        }

        // causal mask + stage into Ps
        #pragma unroll
        for (int i = 0; i < 4; i++) {
            int ig = q0 + ty + i * 16;
            #pragma unroll
            for (int j = 0; j < 4; j++) {
                int jg = kb * BNK + tx + j * 16;
                float v = s[i][j] * scale;
                Ps[(ty + i * 16) * 65 + tx + j * 16] = (jg <= ig) ? v : -1e30f;
            }
        }
        __syncthreads();

        // online softmax per row (64 threads, one row each)
        if (tid < 64) {
            int r = tid;
            float mold = m_s[r];
            float mx = mold;
            for (int j = 0; j < BNK; j++) mx = fmaxf(mx, Ps[r * 65 + j]);
            float alpha = __expf(mold - mx);
            float sum = 0.f;
            for (int j = 0; j < BNK; j++) {
                float p = __expf(Ps[r * 65 + j] - mx);
                Ps[r * 65 + j] = p;
                sum += p;
            }
            m_s[r] = mx;
            l_s[r] = l_s[r] * alpha + sum;
            a_s[r] = alpha;
        }
        __syncthreads();

        // acc = acc*alpha + P @ V   (each thread: 4 rows x 8 dims)
        #pragma unroll
        for (int i = 0; i < 4; i++) {
            float alpha = a_s[ty + i * 16];
            #pragma unroll
            for (int j = 0; j < 8; j++) acc[i][j] *= alpha;
        }
        #pragma unroll 2
        for (int j = 0; j < BNK; j++) {
            float p[4], v[8];
            #pragma unroll
            for (int i = 0; i < 4; i++)  p[i]  = Ps[(ty + i * 16) * 65 + j];
            #pragma unroll
            for (int jj = 0; jj < 8; jj++) v[jj] = Vs[j * 129 + tx + jj * 16];
            #pragma unroll
            for (int i = 0; i < 4; i++)
                #pragma unroll
                for (int jj = 0; jj < 8; jj++)
                    acc[i][jj] = fmaf(p[i], v[jj], acc[i][jj]);
        }
    }

    // normalize + write out
    #pragma unroll
    for (int i = 0; i < 4; i++) {
        float inv = 1.f / l_s[ty + i * 16];
        #pragma unroll
        for (int jj = 0; jj < 8; jj++) {
            O[(size_t)(b * SEQT + q0 + ty + i * 16) * DIM + h * HD + tx + jj * 16] =
                acc[i][jj] * inv;
        }
    }
}

// ---------------------------------------------------------------------------
extern "C" void kernel_launch(void* const* d_in, const int* in_sizes, int n_in,
                              void* d_out, int out_size) {
    const float* enc = (const float*)d_in[0];   // [4,2048,2048]
    const float* dec = (const float*)d_in[1];   // [4,2048,2048]
    const float* Wkv = (const float*)d_in[2];   // [2048,4096]
    const float* bkv = (const float*)d_in[3];   // [4096]
    const float* Wq  = (const float*)d_in[4];   // [2048,2048]
    const float* bq  = (const float*)d_in[5];   // [2048]
    const float* Wo  = (const float*)d_in[6];   // [2048,2048]
    const float* bo  = (const float*)d_in[7];   // [2048]
    float* out = (float*)d_out;

    float *KV, *Q, *O;
    cudaGetSymbolAddress((void**)&KV, g_KV);
    cudaGetSymbolAddress((void**)&Q,  g_Q);
    cudaGetSymbolAddress((void**)&O,  g_O);

    // attention kernel needs > 48KB dynamic smem
    int attn_smem = (3 * 64 * 129 + 64 * 65 + 3 * 64) * (int)sizeof(float);
    cudaFuncSetAttribute(attn_kernel, cudaFuncAttributeMaxDynamicSharedMemorySize,
                         attn_smem);

    dim3 blk(256);

    // 1) KV projection: [8192,2048] @ [2048,4096]
    gemm_bias_kernel<<<dim3(TWO_DIM / 128, M_TOK / 128), blk>>>(
        enc, Wkv, bkv, KV, M_TOK, TWO_DIM, DIM);

    // 2) Q projection: [8192,2048] @ [2048,2048]
    gemm_bias_kernel<<<dim3(DIM / 128, M_TOK / 128), blk>>>(
        dec, Wq, bq, Q, M_TOK, DIM, DIM);

    // 3) causal flash attention
    attn_kernel<<<dim3(SEQT / BMQ, NH, BATCH), blk, attn_smem>>>(Q, KV, O);

    // 4) output projection: [8192,2048] @ [2048,2048]
    gemm_bias_kernel<<<dim3(DIM / 128, M_TOK / 128), blk>>>(
        O, Wo, bo, out, M_TOK, DIM, DIM);
}

// round 3
// speedup vs baseline: 1.8490x; 1.8490x over previous
#include <cuda_runtime.h>
#include <cuda_bf16.h>
#include <cstdint>
#include <math.h>

#define DIM     2048
#define TWO_DIM 4096
#define NH      16
#define HD      128
#define BATCH   4
#define SEQT    2048
#define M_TOK   8192   // BATCH*SEQT

// ---------------- scratch (__device__ globals: allocation-free rule) -------
__device__ float g_KV[(size_t)M_TOK * TWO_DIM];  // K | V fp32
__device__ float g_Q [(size_t)M_TOK * DIM];
__device__ float g_O [(size_t)M_TOK * DIM];

__device__ __nv_bfloat16 g_enc_h[(size_t)M_TOK * DIM];
__device__ __nv_bfloat16 g_enc_l[(size_t)M_TOK * DIM];
__device__ __nv_bfloat16 g_dec_h[(size_t)M_TOK * DIM];
__device__ __nv_bfloat16 g_dec_l[(size_t)M_TOK * DIM];
__device__ __nv_bfloat16 g_ao_h [(size_t)M_TOK * DIM];
__device__ __nv_bfloat16 g_ao_l [(size_t)M_TOK * DIM];
// weights transposed to [N, K] (K-major => col-major B for mma .row.col)
__device__ __nv_bfloat16 g_wkv_h[(size_t)TWO_DIM * DIM];
__device__ __nv_bfloat16 g_wkv_l[(size_t)TWO_DIM * DIM];
__device__ __nv_bfloat16 g_wq_h [(size_t)DIM * DIM];
__device__ __nv_bfloat16 g_wq_l [(size_t)DIM * DIM];
__device__ __nv_bfloat16 g_wo_h [(size_t)DIM * DIM];
__device__ __nv_bfloat16 g_wo_l [(size_t)DIM * DIM];

// ---------------- helpers ---------------------------------------------------
__device__ __forceinline__ uint32_t smem_u32(const void* p) {
    uint32_t a;
    asm("{ .reg .u64 t; cvta.to.shared.u64 t, %1; cvt.u32.u64 %0, t; }" : "=r"(a) : "l"(p));
    return a;
}
__device__ __forceinline__ void cp_async16(uint32_t dst, const void* src) {
    asm volatile("cp.async.cg.shared.global [%0], [%1], 16;" :: "r"(dst), "l"(src));
}
#define CP_COMMIT() asm volatile("cp.async.commit_group;" ::: "memory")

__device__ __forceinline__ void mma16816(float* d, const uint32_t* a, const uint32_t* b) {
    asm volatile(
        "mma.sync.aligned.m16n8k16.row.col.f32.bf16.bf16.f32 "
        "{%0,%1,%2,%3}, {%4,%5,%6,%7}, {%8,%9}, {%0,%1,%2,%3};\n"
        : "+f"(d[0]), "+f"(d[1]), "+f"(d[2]), "+f"(d[3])
        : "r"(a[0]), "r"(a[1]), "r"(a[2]), "r"(a[3]), "r"(b[0]), "r"(b[1]));
}
__device__ __forceinline__ uint32_t lds32(const __nv_bfloat16* p) {
    return *reinterpret_cast<const uint32_t*>(p);
}

// ---------------- split conversion kernels ---------------------------------
__global__ __launch_bounds__(256)
void split_kernel(const float* __restrict__ x, __nv_bfloat16* __restrict__ h,
                  __nv_bfloat16* __restrict__ l, int n4) {
    int i = blockIdx.x * blockDim.x + threadIdx.x;
    if (i >= n4) return;
    float4 v = ((const float4*)x)[i];
    __nv_bfloat16 h0 = __float2bfloat16(v.x), h1 = __float2bfloat16(v.y);
    __nv_bfloat16 h2 = __float2bfloat16(v.z), h3 = __float2bfloat16(v.w);
    __nv_bfloat16 l0 = __float2bfloat16(v.x - __bfloat162float(h0));
    __nv_bfloat16 l1 = __float2bfloat16(v.y - __bfloat162float(h1));
    __nv_bfloat16 l2 = __float2bfloat16(v.z - __bfloat162float(h2));
    __nv_bfloat16 l3 = __float2bfloat16(v.w - __bfloat162float(h3));
    ((__nv_bfloat162*)h)[2 * i]     = __halves2bfloat162(h0, h1);
    ((__nv_bfloat162*)h)[2 * i + 1] = __halves2bfloat162(h2, h3);
    ((__nv_bfloat162*)l)[2 * i]     = __halves2bfloat162(l0, l1);
    ((__nv_bfloat162*)l)[2 * i + 1] = __halves2bfloat162(l2, l3);
}

// W[K,N] fp32 -> WT hi/lo [N,K] bf16
__global__ __launch_bounds__(256)
void splitT_kernel(const float* __restrict__ W, __nv_bfloat16* __restrict__ h,
                   __nv_bfloat16* __restrict__ l, int K, int N) {
    __shared__ float t[32][33];
    int n0 = blockIdx.x * 32, k0 = blockIdx.y * 32;
    int tx = threadIdx.x & 31, ty = threadIdx.x >> 5;
    #pragma unroll
    for (int i = 0; i < 32; i += 8)
        t[ty + i][tx] = W[(size_t)(k0 + ty + i) * N + n0 + tx];
    __syncthreads();
    #pragma unroll
    for (int i = 0; i < 32; i += 8) {
        float v = t[tx][ty + i];
        __nv_bfloat16 hh = __float2bfloat16(v);
        __nv_bfloat16 ll = __float2bfloat16(v - __bfloat162float(hh));
        size_t o = (size_t)(n0 + ty + i) * K + k0 + tx;
        h[o] = hh;
        l[o] = ll;
    }
}

// ---------------- mma.sync split-bf16 GEMM ----------------------------------
// C[M,N] = A[M,K] @ Bt^T + bias, Bt is [N,K] K-major.
// CTA 128x128, 8 warps (2m x 4n), warp tile 64x32.  BK=32, 2-stage cp.async.
// Smem rows padded to 40 bf16 (80B stride) => conflict-free fragment loads.
#define BK        32
#define ROWQ      40                      // padded row length (bf16)
#define ARR_ELEMS (128 * ROWQ)            // 5120 bf16 per array
#define STAGE_ELEMS (4 * ARR_ELEMS)       // Ah,Al,Bh,Bl
#define GT_SMEM   (2 * STAGE_ELEMS * 2)   // bytes = 81920

__device__ __forceinline__ void load_chunk(uint32_t sbase,
    const __nv_bfloat16* Ah, const __nv_bfloat16* Al,
    const __nv_bfloat16* Bh, const __nv_bfloat16* Bl,
    int K, int kt, int tid)
{
    #pragma unroll
    for (int i = 0; i < 2; i++) {
        int idx = i * 256 + tid;          // 0..511
        int r = idx >> 2, c = idx & 3;    // row 0..127, 16B seg 0..3
        uint32_t doff = (uint32_t)(r * ROWQ + c * 8) * 2;   // bytes
        size_t   soff = (size_t)r * K + kt + c * 8;
        cp_async16(sbase + doff,                     Ah + soff);
        cp_async16(sbase + ARR_ELEMS * 2 + doff,     Al + soff);
        cp_async16(sbase + ARR_ELEMS * 4 + doff,     Bh + soff);
        cp_async16(sbase + ARR_ELEMS * 6 + doff,     Bl + soff);
    }
}

__global__ __launch_bounds__(256)
void gemm_tc(const __nv_bfloat16* __restrict__ Ah, const __nv_bfloat16* __restrict__ Al,
             const __nv_bfloat16* __restrict__ Bth, const __nv_bfloat16* __restrict__ Btl,
             const float* __restrict__ bias, float* __restrict__ C,
             int M, int N, int K)
{
    extern __shared__ __align__(16) __nv_bfloat16 sm_g[];
    uint32_t sbase = smem_u32(sm_g);
    int tid = threadIdx.x, wid = tid >> 5, lid = tid & 31;
    int g = lid >> 2, t = lid & 3;
    int wm = (wid & 1) * 64;        // warp m offset in CTA tile
    int wn = (wid >> 1) * 32;       // warp n offset
    int m0 = blockIdx.y * 128, n0 = blockIdx.x * 128;

    const __nv_bfloat16* A_h = Ah  + (size_t)m0 * K;
    const __nv_bfloat16* A_l = Al  + (size_t)m0 * K;
    const __nv_bfloat16* B_h = Bth + (size_t)n0 * K;
    const __nv_bfloat16* B_l = Btl + (size_t)n0 * K;

    float acc[4][4][4];
    #pragma unroll
    for (int i = 0; i < 4; i++)
        #pragma unroll
        for (int j = 0; j < 4; j++)
            #pragma unroll
            for (int r = 0; r < 4; r++) acc[i][j][r] = 0.f;

    const int NCH = K / BK;   // 64

    load_chunk(sbase,                   A_h, A_l, B_h, B_l, K, 0,  tid);
    CP_COMMIT();
    load_chunk(sbase + STAGE_ELEMS * 2, A_h, A_l, B_h, B_l, K, BK, tid);
    CP_COMMIT();

    for (int c = 0; c < NCH; c++) {
        int s = c & 1;
        if (c == NCH - 1) asm volatile("cp.async.wait_group 0;" ::: "memory");
        else              asm volatile("cp.async.wait_group 1;" ::: "memory");
        __syncthreads();

        const __nv_bfloat16* stg = sm_g + (size_t)s * STAGE_ELEMS;
        const __nv_bfloat16* sAh = stg;
        const __nv_bfloat16* sAl = stg + ARR_ELEMS;
        const __nv_bfloat16* sBh = stg + 2 * ARR_ELEMS;
        const __nv_bfloat16* sBl = stg + 3 * ARR_ELEMS;

        #pragma unroll
        for (int ks = 0; ks < BK; ks += 16) {
            uint32_t ah[4][4], al[4][4], bh[4][2], bl[4][2];
            #pragma unroll
            for (int mi = 0; mi < 4; mi++) {
                const __nv_bfloat16* p = sAh + (wm + mi * 16 + g) * ROWQ + ks + t * 2;
                ah[mi][0] = lds32(p);
                ah[mi][1] = lds32(p + 8 * ROWQ);
                ah[mi][2] = lds32(p + 8);
                ah[mi][3] = lds32(p + 8 * ROWQ + 8);
                const __nv_bfloat16* q = sAl + (wm + mi * 16 + g) * ROWQ + ks + t * 2;
                al[mi][0] = lds32(q);
                al[mi][1] = lds32(q + 8 * ROWQ);
                al[mi][2] = lds32(q + 8);
                al[mi][3] = lds32(q + 8 * ROWQ + 8);
            }
            #pragma unroll
            for (int nj = 0; nj < 4; nj++) {
                const __nv_bfloat16* p = sBh + (wn + nj * 8 + g) * ROWQ + ks + t * 2;
                bh[nj][0] = lds32(p);
                bh[nj][1] = lds32(p + 8);
                const __nv_bfloat16* q = sBl + (wn + nj * 8 + g) * ROWQ + ks + t * 2;
                bl[nj][0] = lds32(q);
                bl[nj][1] = lds32(q + 8);
            }
            #pragma unroll
            for (int mi = 0; mi < 4; mi++)
                #pragma unroll
                for (int nj = 0; nj < 4; nj++) {
                    mma16816(acc[mi][nj], ah[mi], bh[nj]);
                    mma16816(acc[mi][nj], ah[mi], bl[nj]);
                    mma16816(acc[mi][nj], al[mi], bh[nj]);
                }
        }
        __syncthreads();

        if (c + 2 < NCH) {
            load_chunk(sbase + (uint32_t)s * STAGE_ELEMS * 2,
                       A_h, A_l, B_h, B_l, K, (c + 2) * BK, tid);
            CP_COMMIT();
        }
    }

    // epilogue: bias + store (d0,d1 -> row, cols 2t,2t+1; d2,d3 -> row+8)
    #pragma unroll
    for (int nj = 0; nj < 4; nj++) {
        int col = n0 + wn + nj * 8 + t * 2;
        float b0 = bias[col], b1 = bias[col + 1];
        #pragma unroll
        for (int mi = 0; mi < 4; mi++) {
            int row = m0 + wm + mi * 16 + g;
            float2 v0 = make_float2(acc[mi][nj][0] + b0, acc[mi][nj][1] + b1);
            float2 v1 = make_float2(acc[mi][nj][2] + b0, acc[mi][nj][3] + b1);
            *(float2*)(C + (size_t)row * N + col)       = v0;
            *(float2*)(C + (size_t)(row + 8) * N + col) = v1;
        }
    }
}

// ---------------- causal flash attention (fp32, unchanged) -----------------
#define BMQ 64
#define BNK 64

__global__ __launch_bounds__(256)
void attn_kernel(const float* __restrict__ Q, const float* __restrict__ KV,
                 float* __restrict__ O) {
    extern __shared__ float sm[];
    float* Qs  = sm;
    float* Ks  = Qs + 64 * 129;
    float* Vs  = Ks + 64 * 129;
    float* Ps  = Vs + 64 * 129;
    float* m_s = Ps + 64 * 65;
    float* l_s = m_s + 64;
    float* a_s = l_s + 64;

    int tid = threadIdx.x;
    int tx = tid & 15;
    int ty = tid >> 4;
    int qb = blockIdx.x, h = blockIdx.y, b = blockIdx.z;
    int q0 = qb * BMQ;
    const float scale = 0.08838834764831845f;

    for (int idx = tid; idx < BMQ * HD; idx += 256) {
        int r = idx >> 7, c = idx & 127;
        Qs[r * 129 + c] = Q[(size_t)(b * SEQT + q0 + r) * DIM + h * HD + c];
    }
    if (tid < 64) { m_s[tid] = -1e30f; l_s[tid] = 0.f; }

    float acc[4][8];
    #pragma unroll
    for (int i = 0; i < 4; i++)
        #pragma unroll
        for (int j = 0; j < 8; j++) acc[i][j] = 0.f;

    int nkb = qb + 1;
    for (int kb = 0; kb < nkb; kb++) {
        __syncthreads();
        for (int idx = tid; idx < BNK * HD; idx += 256) {
            int r = idx >> 7, c = idx & 127;
            size_t base = (size_t)(b * SEQT + kb * BNK + r) * TWO_DIM + h * HD + c;
            Ks[r * 129 + c] = KV[base];
            Vs[r * 129 + c] = KV[base + DIM];
        }
        __syncthreads();

        float s[4][4];
        #pragma unroll
        for (int i = 0; i < 4; i++)
            #pragma unroll
            for (int j = 0; j < 4; j++) s[i][j] = 0.f;

        #pragma unroll 4
        for (int d = 0; d < HD; d++) {
            float a[4], bk[4];
            #pragma unroll
            for (int i = 0; i < 4; i++) a[i]  = Qs[(ty + i * 16) * 129 + d];
            #pragma unroll
            for (int j = 0; j < 4; j++) bk[j] = Ks[(tx + j * 16) * 129 + d];
            #pragma unroll
            for (int i = 0; i < 4; i++)
                #pragma unroll
                for (int j = 0; j < 4; j++)
                    s[i][j] = fmaf(a[i], bk[j], s[i][j]);
        }

        #pragma unroll
        for (int i = 0; i < 4; i++) {
            int ig = q0 + ty + i * 16;
            #pragma unroll
            for (int j = 0; j < 4; j++) {
                int jg = kb * BNK + tx + j * 16;
                float v = s[i][j] * scale;
                Ps[(ty + i * 16) * 65 + tx + j * 16] = (jg <= ig) ? v : -1e30f;
            }
        }
        __syncthreads();

        if (tid < 64) {
            int r = tid;
            float mold = m_s[r];
            float mx = mold;
            for (int j = 0; j < BNK; j++) mx = fmaxf(mx, Ps[r * 65 + j]);
            float alpha = __expf(mold - mx);
            float sum = 0.f;
            for (int j = 0; j < BNK; j++) {
                float p = __expf(Ps[r * 65 + j] - mx);
                Ps[r * 65 + j] = p;
                sum += p;
            }
            m_s[r] = mx;
            l_s[r] = l_s[r] * alpha + sum;
            a_s[r] = alpha;
        }
        __syncthreads();

        #pragma unroll
        for (int i = 0; i < 4; i++) {
            float alpha = a_s[ty + i * 16];
            #pragma unroll
            for (int j = 0; j < 8; j++) acc[i][j] *= alpha;
        }
        #pragma unroll 2
        for (int j = 0; j < BNK; j++) {
            float p[4], v[8];
            #pragma unroll
            for (int i = 0; i < 4; i++)  p[i]  = Ps[(ty + i * 16) * 65 + j];
            #pragma unroll
            for (int jj = 0; jj < 8; jj++) v[jj] = Vs[j * 129 + tx + jj * 16];
            #pragma unroll
            for (int i = 0; i < 4; i++)
                #pragma unroll
                for (int jj = 0; jj < 8; jj++)
                    acc[i][jj] = fmaf(p[i], v[jj], acc[i][jj]);
        }
    }

    #pragma unroll
    for (int i = 0; i < 4; i++) {
        float inv = 1.f / l_s[ty + i * 16];
        #pragma unroll
        for (int jj = 0; jj < 8; jj++) {
            O[(size_t)(b * SEQT + q0 + ty + i * 16) * DIM + h * HD + tx + jj * 16] =
                acc[i][jj] * inv;
        }
    }
}

// ---------------------------------------------------------------------------
extern "C" void kernel_launch(void* const* d_in, const int* in_sizes, int n_in,
                              void* d_out, int out_size) {
    const float* enc = (const float*)d_in[0];
    const float* dec = (const float*)d_in[1];
    const float* Wkv = (const float*)d_in[2];
    const float* bkv = (const float*)d_in[3];
    const float* Wq  = (const float*)d_in[4];
    const float* bq  = (const float*)d_in[5];
    const float* Wo  = (const float*)d_in[6];
    const float* bo  = (const float*)d_in[7];
    float* out = (float*)d_out;

    float *KV, *Q, *O;
    cudaGetSymbolAddress((void**)&KV, g_KV);
    cudaGetSymbolAddress((void**)&Q,  g_Q);
    cudaGetSymbolAddress((void**)&O,  g_O);
    __nv_bfloat16 *eh, *el, *dh, *dl, *aoh, *aol, *wkvh, *wkvl, *wqh, *wql, *woh, *wol;
    cudaGetSymbolAddress((void**)&eh,  g_enc_h);  cudaGetSymbolAddress((void**)&el,  g_enc_l);
    cudaGetSymbolAddress((void**)&dh,  g_dec_h);  cudaGetSymbolAddress((void**)&dl,  g_dec_l);
    cudaGetSymbolAddress((void**)&aoh, g_ao_h);   cudaGetSymbolAddress((void**)&aol, g_ao_l);
    cudaGetSymbolAddress((void**)&wkvh, g_wkv_h); cudaGetSymbolAddress((void**)&wkvl, g_wkv_l);
    cudaGetSymbolAddress((void**)&wqh, g_wq_h);   cudaGetSymbolAddress((void**)&wql, g_wq_l);
    cudaGetSymbolAddress((void**)&woh, g_wo_h);   cudaGetSymbolAddress((void**)&wol, g_wo_l);

    int attn_smem = (3 * 64 * 129 + 64 * 65 + 3 * 64) * (int)sizeof(float);
    cudaFuncSetAttribute(attn_kernel, cudaFuncAttributeMaxDynamicSharedMemorySize, attn_smem);
    cudaFuncSetAttribute(gemm_tc, cudaFuncAttributeMaxDynamicSharedMemorySize, GT_SMEM);

    int n4_act = (M_TOK * DIM) / 4;

    // split activations + weights
    split_kernel<<<(n4_act + 255) / 256, 256>>>(enc, eh, el, n4_act);
    split_kernel<<<(n4_act + 255) / 256, 256>>>(dec, dh, dl, n4_act);
    splitT_kernel<<<dim3(TWO_DIM / 32, DIM / 32), 256>>>(Wkv, wkvh, wkvl, DIM, TWO_DIM);
    splitT_kernel<<<dim3(DIM / 32,     DIM / 32), 256>>>(Wq,  wqh,  wql,  DIM, DIM);
    splitT_kernel<<<dim3(DIM / 32,     DIM / 32), 256>>>(Wo,  woh,  wol,  DIM, DIM);

    // KV projection: [8192,2048] @ [2048,4096]
    gemm_tc<<<dim3(TWO_DIM / 128, M_TOK / 128), 256, GT_SMEM>>>(
        eh, el, wkvh, wkvl, bkv, KV, M_TOK, TWO_DIM, DIM);
    // Q projection
    gemm_tc<<<dim3(DIM / 128, M_TOK / 128), 256, GT_SMEM>>>(
        dh, dl, wqh, wql, bq, Q, M_TOK, DIM, DIM);

    // attention (fp32)
    attn_kernel<<<dim3(SEQT / BMQ, NH, BATCH), 256, attn_smem>>>(Q, KV, O);

    // split attention output, then O projection
    split_kernel<<<(n4_act + 255) / 256, 256>>>(O, aoh, aol, n4_act);
    gemm_tc<<<dim3(DIM / 128, M_TOK / 128), 256, GT_SMEM>>>(
        aoh, aol, woh, wol, bo, out, M_TOK, DIM, DIM);
}

// round 4
// speedup vs baseline: 3.3190x; 1.7950x over previous
#include <cuda_runtime.h>
#include <cuda_bf16.h>
#include <cstdint>
#include <math.h>

#define DIM     2048
#define TWO_DIM 4096
#define NH      16
#define HD      128
#define BATCH   4
#define SEQT    2048
#define M_TOK   8192   // BATCH*SEQT

// ---------------- scratch (__device__ globals: allocation-free rule) -------
__device__ __nv_bfloat16 g_enc_h[(size_t)M_TOK * DIM];
__device__ __nv_bfloat16 g_enc_l[(size_t)M_TOK * DIM];
__device__ __nv_bfloat16 g_dec_h[(size_t)M_TOK * DIM];
__device__ __nv_bfloat16 g_dec_l[(size_t)M_TOK * DIM];
__device__ __nv_bfloat16 g_kv_h [(size_t)M_TOK * TWO_DIM];
__device__ __nv_bfloat16 g_kv_l [(size_t)M_TOK * TWO_DIM];
__device__ __nv_bfloat16 g_q_h  [(size_t)M_TOK * DIM];
__device__ __nv_bfloat16 g_q_l  [(size_t)M_TOK * DIM];
__device__ __nv_bfloat16 g_ao_h [(size_t)M_TOK * DIM];
__device__ __nv_bfloat16 g_ao_l [(size_t)M_TOK * DIM];
// weights transposed to [N, K] (K-major => col-major B for mma .row.col)
__device__ __nv_bfloat16 g_wkv_h[(size_t)TWO_DIM * DIM];
__device__ __nv_bfloat16 g_wkv_l[(size_t)TWO_DIM * DIM];
__device__ __nv_bfloat16 g_wq_h [(size_t)DIM * DIM];
__device__ __nv_bfloat16 g_wq_l [(size_t)DIM * DIM];
__device__ __nv_bfloat16 g_wo_h [(size_t)DIM * DIM];
__device__ __nv_bfloat16 g_wo_l [(size_t)DIM * DIM];

// ---------------- helpers ---------------------------------------------------
__device__ __forceinline__ uint32_t smem_u32(const void* p) {
    uint32_t a;
    asm("{ .reg .u64 t; cvta.to.shared.u64 t, %1; cvt.u32.u64 %0, t; }" : "=r"(a) : "l"(p));
    return a;
}
__device__ __forceinline__ void cp_async16(uint32_t dst, const void* src) {
    asm volatile("cp.async.cg.shared.global [%0], [%1], 16;" :: "r"(dst), "l"(src));
}
#define CP_COMMIT() asm volatile("cp.async.commit_group;" ::: "memory")

__device__ __forceinline__ void mma16816(float* d, const uint32_t* a, const uint32_t* b) {
    asm volatile(
        "mma.sync.aligned.m16n8k16.row.col.f32.bf16.bf16.f32 "
        "{%0,%1,%2,%3}, {%4,%5,%6,%7}, {%8,%9}, {%0,%1,%2,%3};\n"
        : "+f"(d[0]), "+f"(d[1]), "+f"(d[2]), "+f"(d[3])
        : "r"(a[0]), "r"(a[1]), "r"(a[2]), "r"(a[3]), "r"(b[0]), "r"(b[1]));
}
__device__ __forceinline__ uint32_t lds32(const __nv_bfloat16* p) {
    return *reinterpret_cast<const uint32_t*>(p);
}
__device__ __forceinline__ void ldsm4t(uint32_t* r, uint32_t saddr) {
    asm volatile("ldmatrix.sync.aligned.m8n8.x4.trans.shared.b16 {%0,%1,%2,%3}, [%4];"
        : "=r"(r[0]), "=r"(r[1]), "=r"(r[2]), "=r"(r[3]) : "r"(saddr));
}
__device__ __forceinline__ uint32_t pack_hi(float v0, float v1, float& r0, float& r1) {
    __nv_bfloat162 h = __floats2bfloat162_rn(v0, v1);
    r0 = v0 - __bfloat162float(h.x);
    r1 = v1 - __bfloat162float(h.y);
    return *reinterpret_cast<uint32_t*>(&h);
}
__device__ __forceinline__ uint32_t pack_bf2(float v0, float v1) {
    __nv_bfloat162 h = __floats2bfloat162_rn(v0, v1);
    return *reinterpret_cast<uint32_t*>(&h);
}

// ---------------- split conversion kernels ---------------------------------
__global__ __launch_bounds__(256)
void split_kernel(const float* __restrict__ x, __nv_bfloat16* __restrict__ h,
                  __nv_bfloat16* __restrict__ l, int n4) {
    int i = blockIdx.x * blockDim.x + threadIdx.x;
    if (i >= n4) return;
    float4 v = ((const float4*)x)[i];
    __nv_bfloat16 h0 = __float2bfloat16(v.x), h1 = __float2bfloat16(v.y);
    __nv_bfloat16 h2 = __float2bfloat16(v.z), h3 = __float2bfloat16(v.w);
    __nv_bfloat16 l0 = __float2bfloat16(v.x - __bfloat162float(h0));
    __nv_bfloat16 l1 = __float2bfloat16(v.y - __bfloat162float(h1));
    __nv_bfloat16 l2 = __float2bfloat16(v.z - __bfloat162float(h2));
    __nv_bfloat16 l3 = __float2bfloat16(v.w - __bfloat162float(h3));
    ((__nv_bfloat162*)h)[2 * i]     = __halves2bfloat162(h0, h1);
    ((__nv_bfloat162*)h)[2 * i + 1] = __halves2bfloat162(h2, h3);
    ((__nv_bfloat162*)l)[2 * i]     = __halves2bfloat162(l0, l1);
    ((__nv_bfloat162*)l)[2 * i + 1] = __halves2bfloat162(l2, l3);
}

// W[K,N] fp32 -> WT hi/lo [N,K] bf16
__global__ __launch_bounds__(256)
void splitT_kernel(const float* __restrict__ W, __nv_bfloat16* __restrict__ h,
                   __nv_bfloat16* __restrict__ l, int K, int N) {
    __shared__ float t[32][33];
    int n0 = blockIdx.x * 32, k0 = blockIdx.y * 32;
    int tx = threadIdx.x & 31, ty = threadIdx.x >> 5;
    #pragma unroll
    for (int i = 0; i < 32; i += 8)
        t[ty + i][tx] = W[(size_t)(k0 + ty + i) * N + n0 + tx];
    __syncthreads();
    #pragma unroll
    for (int i = 0; i < 32; i += 8) {
        float v = t[tx][ty + i];
        __nv_bfloat16 hh = __float2bfloat16(v);
        __nv_bfloat16 ll = __float2bfloat16(v - __bfloat162float(hh));
        size_t o = (size_t)(n0 + ty + i) * K + k0 + tx;
        h[o] = hh;
        l[o] = ll;
    }
}

// ---------------- mma.sync split-bf16 GEMM ----------------------------------
// C = A @ Bt^T + bias.  mode 0: fp32 out to Cf.  mode 1: scale*(acc+bias),
// split into bf16 hi/lo written to Ch/Cl.
#define BK        32
#define ROWQ      40
#define ARR_ELEMS (128 * ROWQ)
#define STAGE_ELEMS (4 * ARR_ELEMS)
#define GT_SMEM   (2 * STAGE_ELEMS * 2)

__device__ __forceinline__ void load_chunk(uint32_t sbase,
    const __nv_bfloat16* Ah, const __nv_bfloat16* Al,
    const __nv_bfloat16* Bh, const __nv_bfloat16* Bl,
    int K, int kt, int tid)
{
    #pragma unroll
    for (int i = 0; i < 2; i++) {
        int idx = i * 256 + tid;
        int r = idx >> 2, c = idx & 3;
        uint32_t doff = (uint32_t)(r * ROWQ + c * 8) * 2;
        size_t   soff = (size_t)r * K + kt + c * 8;
        cp_async16(sbase + doff,                 Ah + soff);
        cp_async16(sbase + ARR_ELEMS * 2 + doff, Al + soff);
        cp_async16(sbase + ARR_ELEMS * 4 + doff, Bh + soff);
        cp_async16(sbase + ARR_ELEMS * 6 + doff, Bl + soff);
    }
}

__global__ __launch_bounds__(256)
void gemm_tc(const __nv_bfloat16* __restrict__ Ah, const __nv_bfloat16* __restrict__ Al,
             const __nv_bfloat16* __restrict__ Bth, const __nv_bfloat16* __restrict__ Btl,
             const float* __restrict__ bias, float scale,
             float* __restrict__ Cf,
             __nv_bfloat16* __restrict__ Ch, __nv_bfloat16* __restrict__ Cl,
             int mode, int M, int N, int K)
{
    extern __shared__ __align__(16) __nv_bfloat16 sm_g[];
    uint32_t sbase = smem_u32(sm_g);
    int tid = threadIdx.x, wid = tid >> 5, lid = tid & 31;
    int g = lid >> 2, t = lid & 3;
    int wm = (wid & 1) * 64;
    int wn = (wid >> 1) * 32;
    int m0 = blockIdx.y * 128, n0 = blockIdx.x * 128;

    const __nv_bfloat16* A_h = Ah  + (size_t)m0 * K;
    const __nv_bfloat16* A_l = Al  + (size_t)m0 * K;
    const __nv_bfloat16* B_h = Bth + (size_t)n0 * K;
    const __nv_bfloat16* B_l = Btl + (size_t)n0 * K;

    float acc[4][4][4];
    #pragma unroll
    for (int i = 0; i < 4; i++)
        #pragma unroll
        for (int j = 0; j < 4; j++)
            #pragma unroll
            for (int r = 0; r < 4; r++) acc[i][j][r] = 0.f;

    const int NCH = K / BK;

    load_chunk(sbase,                   A_h, A_l, B_h, B_l, K, 0,  tid);
    CP_COMMIT();
    load_chunk(sbase + STAGE_ELEMS * 2, A_h, A_l, B_h, B_l, K, BK, tid);
    CP_COMMIT();

    for (int c = 0; c < NCH; c++) {
        int s = c & 1;
        if (c == NCH - 1) asm volatile("cp.async.wait_group 0;" ::: "memory");
        else              asm volatile("cp.async.wait_group 1;" ::: "memory");
        __syncthreads();

        const __nv_bfloat16* stg = sm_g + (size_t)s * STAGE_ELEMS;
        const __nv_bfloat16* sAh = stg;
        const __nv_bfloat16* sAl = stg + ARR_ELEMS;
        const __nv_bfloat16* sBh = stg + 2 * ARR_ELEMS;
        const __nv_bfloat16* sBl = stg + 3 * ARR_ELEMS;

        #pragma unroll
        for (int ks = 0; ks < BK; ks += 16) {
            uint32_t ah[4][4], al[4][4], bh[4][2], bl[4][2];
            #pragma unroll
            for (int mi = 0; mi < 4; mi++) {
                const __nv_bfloat16* p = sAh + (wm + mi * 16 + g) * ROWQ + ks + t * 2;
                ah[mi][0] = lds32(p);
                ah[mi][1] = lds32(p + 8 * ROWQ);
                ah[mi][2] = lds32(p + 8);
                ah[mi][3] = lds32(p + 8 * ROWQ + 8);
                const __nv_bfloat16* q = sAl + (wm + mi * 16 + g) * ROWQ + ks + t * 2;
                al[mi][0] = lds32(q);
                al[mi][1] = lds32(q + 8 * ROWQ);
                al[mi][2] = lds32(q + 8);
                al[mi][3] = lds32(q + 8 * ROWQ + 8);
            }
            #pragma unroll
            for (int nj = 0; nj < 4; nj++) {
                const __nv_bfloat16* p = sBh + (wn + nj * 8 + g) * ROWQ + ks + t * 2;
                bh[nj][0] = lds32(p);
                bh[nj][1] = lds32(p + 8);
                const __nv_bfloat16* q = sBl + (wn + nj * 8 + g) * ROWQ + ks + t * 2;
                bl[nj][0] = lds32(q);
                bl[nj][1] = lds32(q + 8);
            }
            #pragma unroll
            for (int mi = 0; mi < 4; mi++)
                #pragma unroll
                for (int nj = 0; nj < 4; nj++) {
                    mma16816(acc[mi][nj], ah[mi], bh[nj]);
                    mma16816(acc[mi][nj], ah[mi], bl[nj]);
                    mma16816(acc[mi][nj], al[mi], bh[nj]);
                }
        }
        __syncthreads();

        if (c + 2 < NCH) {
            load_chunk(sbase + (uint32_t)s * STAGE_ELEMS * 2,
                       A_h, A_l, B_h, B_l, K, (c + 2) * BK, tid);
            CP_COMMIT();
        }
    }

    #pragma unroll
    for (int nj = 0; nj < 4; nj++) {
        int col = n0 + wn + nj * 8 + t * 2;
        float b0 = bias[col], b1 = bias[col + 1];
        #pragma unroll
        for (int mi = 0; mi < 4; mi++) {
            int row = m0 + wm + mi * 16 + g;
            if (mode == 0) {
                float2 v0 = make_float2(acc[mi][nj][0] + b0, acc[mi][nj][1] + b1);
                float2 v1 = make_float2(acc[mi][nj][2] + b0, acc[mi][nj][3] + b1);
                *(float2*)(Cf + (size_t)row * N + col)       = v0;
                *(float2*)(Cf + (size_t)(row + 8) * N + col) = v1;
            } else {
                float v0 = (acc[mi][nj][0] + b0) * scale;
                float v1 = (acc[mi][nj][1] + b1) * scale;
                float v2 = (acc[mi][nj][2] + b0) * scale;
                float v3 = (acc[mi][nj][3] + b1) * scale;
                float r0, r1, r2, r3;
                uint32_t h01 = pack_hi(v0, v1, r0, r1);
                uint32_t h23 = pack_hi(v2, v3, r2, r3);
                *(uint32_t*)(Ch + (size_t)row * N + col)       = h01;
                *(uint32_t*)(Ch + (size_t)(row + 8) * N + col) = h23;
                *(uint32_t*)(Cl + (size_t)row * N + col)       = pack_bf2(r0, r1);
                *(uint32_t*)(Cl + (size_t)(row + 8) * N + col) = pack_bf2(r2, r3);
            }
        }
    }
}

// ---------------- split-bf16 mma flash attention ----------------------------
// CTA: 64 q rows (qb), one (h, b). 4 warps x 16 q rows. BN=64 keys/iter.
#define AT_ROWP 136
#define AT_Q_OFF  0
#define AT_QL_OFF (64 * AT_ROWP)
#define AT_K_OFF  (2 * 64 * AT_ROWP)
#define AT_KL_OFF (3 * 64 * AT_ROWP)
#define AT_V_OFF  (4 * 64 * AT_ROWP)
#define AT_VL_OFF (5 * 64 * AT_ROWP)
#define AT_SMEM   (6 * 64 * AT_ROWP * 2)   // 104448 bytes

__global__ __launch_bounds__(128)
void attn_mma(const __nv_bfloat16* __restrict__ Qh, const __nv_bfloat16* __restrict__ Ql,
              const __nv_bfloat16* __restrict__ KVh, const __nv_bfloat16* __restrict__ KVl,
              __nv_bfloat16* __restrict__ Oh, __nv_bfloat16* __restrict__ Ol)
{
    extern __shared__ __align__(16) __nv_bfloat16 sa[];
    uint32_t sb = smem_u32(sa);
    int tid = threadIdx.x, wid = tid >> 5, lid = tid & 31;
    int g = lid >> 2, t = lid & 3;
    int qb = blockIdx.x, h = blockIdx.y, b = blockIdx.z;
    int q0 = qb * 64;

    // ---- load Q tile (pre-scaled hi/lo) ----
    {
        const __nv_bfloat16* srcH = Qh + (size_t)(b * SEQT + q0) * DIM + h * HD;
        const __nv_bfloat16* srcL = Ql + (size_t)(b * SEQT + q0) * DIM + h * HD;
        #pragma unroll
        for (int i = 0; i < 8; i++) {
            int idx = i * 128 + tid;
            int r = idx >> 4, seg = idx & 15;
            uint32_t doff = (uint32_t)(r * AT_ROWP + seg * 8) * 2;
            size_t goff = (size_t)r * DIM + seg * 8;
            cp_async16(sb + AT_Q_OFF * 2 + doff,  srcH + goff);
            cp_async16(sb + AT_QL_OFF * 2 + doff, srcL + goff);
        }
        CP_COMMIT();
    }

    float m0 = -1e30f, m1 = -1e30f, l0 = 0.f, l1 = 0.f;
    float po[16][4];
    #pragma unroll
    for (int i = 0; i < 16; i++)
        #pragma unroll
        for (int r = 0; r < 4; r++) po[i][r] = 0.f;

    const __nv_bfloat16* sQh = sa + AT_Q_OFF;
    const __nv_bfloat16* sQl = sa + AT_QL_OFF;
    const __nv_bfloat16* sKh = sa + AT_K_OFF;
    const __nv_bfloat16* sKl = sa + AT_KL_OFF;

    for (int kb = 0; kb <= qb; kb++) {
        if (kb > 0) __syncthreads();   // prior compute done before overwrite
        {
            const __nv_bfloat16* srcH = KVh + (size_t)(b * SEQT + kb * 64) * TWO_DIM + h * HD;
            const __nv_bfloat16* srcL = KVl + (size_t)(b * SEQT + kb * 64) * TWO_DIM + h * HD;
            #pragma unroll
            for (int i = 0; i < 8; i++) {
                int idx = i * 128 + tid;
                int r = idx >> 4, seg = idx & 15;
                uint32_t doff = (uint32_t)(r * AT_ROWP + seg * 8) * 2;
                size_t goff = (size_t)r * TWO_DIM + seg * 8;
                cp_async16(sb + AT_K_OFF * 2 + doff,  srcH + goff);
                cp_async16(sb + AT_KL_OFF * 2 + doff, srcL + goff);
                cp_async16(sb + AT_V_OFF * 2 + doff,  srcH + DIM + goff);
                cp_async16(sb + AT_VL_OFF * 2 + doff, srcL + DIM + goff);
            }
            CP_COMMIT();
        }
        asm volatile("cp.async.wait_group 0;" ::: "memory");
        __syncthreads();

        // ---- S = Q @ K^T (split 3-product) ----
        float sacc[8][4];
        #pragma unroll
        for (int nj = 0; nj < 8; nj++)
            #pragma unroll
            for (int r = 0; r < 4; r++) sacc[nj][r] = 0.f;

        #pragma unroll
        for (int kc = 0; kc < 8; kc++) {
            uint32_t ah[4], al[4];
            const __nv_bfloat16* pq = sQh + (wid * 16 + g) * AT_ROWP + kc * 16 + t * 2;
            ah[0] = lds32(pq);
            ah[1] = lds32(pq + 8 * AT_ROWP);
            ah[2] = lds32(pq + 8);
            ah[3] = lds32(pq + 8 * AT_ROWP + 8);
            const __nv_bfloat16* ql2 = sQl + (wid * 16 + g) * AT_ROWP + kc * 16 + t * 2;
            al[0] = lds32(ql2);
            al[1] = lds32(ql2 + 8 * AT_ROWP);
            al[2] = lds32(ql2 + 8);
            al[3] = lds32(ql2 + 8 * AT_ROWP + 8);
            #pragma unroll
            for (int nj = 0; nj < 8; nj++) {
                uint32_t bh[2], bl[2];
                const __nv_bfloat16* pk = sKh + (nj * 8 + g) * AT_ROWP + kc * 16 + t * 2;
                bh[0] = lds32(pk);
                bh[1] = lds32(pk + 8);
                const __nv_bfloat16* pk2 = sKl + (nj * 8 + g) * AT_ROWP + kc * 16 + t * 2;
                bl[0] = lds32(pk2);
                bl[1] = lds32(pk2 + 8);
                mma16816(sacc[nj], ah, bh);
                mma16816(sacc[nj], ah, bl);
                mma16816(sacc[nj], al, bh);
            }
        }

        // ---- causal mask (diagonal block only) ----
        int ig0 = q0 + wid * 16 + g;
        int ig1 = ig0 + 8;
        if (kb == qb) {
            #pragma unroll
            for (int nj = 0; nj < 8; nj++) {
                int c0 = kb * 64 + nj * 8 + t * 2;
                if (c0     > ig0) sacc[nj][0] = -1e30f;
                if (c0 + 1 > ig0) sacc[nj][1] = -1e30f;
                if (c0     > ig1) sacc[nj][2] = -1e30f;
                if (c0 + 1 > ig1) sacc[nj][3] = -1e30f;
            }
        }

        // ---- online softmax ----
        float rmax0 = -1e30f, rmax1 = -1e30f;
        #pragma unroll
        for (int nj = 0; nj < 8; nj++) {
            rmax0 = fmaxf(rmax0, fmaxf(sacc[nj][0], sacc[nj][1]));
            rmax1 = fmaxf(rmax1, fmaxf(sacc[nj][2], sacc[nj][3]));
        }
        rmax0 = fmaxf(rmax0, __shfl_xor_sync(0xffffffffu, rmax0, 1));
        rmax0 = fmaxf(rmax0, __shfl_xor_sync(0xffffffffu, rmax0, 2));
        rmax1 = fmaxf(rmax1, __shfl_xor_sync(0xffffffffu, rmax1, 1));
        rmax1 = fmaxf(rmax1, __shfl_xor_sync(0xffffffffu, rmax1, 2));
        float mn0 = fmaxf(m0, rmax0), mn1 = fmaxf(m1, rmax1);
        float alpha0 = __expf(m0 - mn0), alpha1 = __expf(m1 - mn1);
        float rs0 = 0.f, rs1 = 0.f;
        #pragma unroll
        for (int nj = 0; nj < 8; nj++) {
            float p0 = __expf(sacc[nj][0] - mn0);
            float p1 = __expf(sacc[nj][1] - mn0);
            float p2 = __expf(sacc[nj][2] - mn1);
            float p3 = __expf(sacc[nj][3] - mn1);
            sacc[nj][0] = p0; sacc[nj][1] = p1; sacc[nj][2] = p2; sacc[nj][3] = p3;
            rs0 += p0 + p1;
            rs1 += p2 + p3;
        }
        rs0 += __shfl_xor_sync(0xffffffffu, rs0, 1);
        rs0 += __shfl_xor_sync(0xffffffffu, rs0, 2);
        rs1 += __shfl_xor_sync(0xffffffffu, rs1, 1);
        rs1 += __shfl_xor_sync(0xffffffffu, rs1, 2);
        l0 = l0 * alpha0 + rs0;
        l1 = l1 * alpha1 + rs1;
        m0 = mn0; m1 = mn1;

        #pragma unroll
        for (int dj = 0; dj < 16; dj++) {
            po[dj][0] *= alpha0; po[dj][1] *= alpha0;
            po[dj][2] *= alpha1; po[dj][3] *= alpha1;
        }

        // ---- O += P @ V (split 3-product, V frags via ldmatrix.trans) ----
        uint32_t vrow = (uint32_t)(lid & 15);
        uint32_t vcolx = (lid & 16) ? 8u : 0u;
        #pragma unroll
        for (int kc2 = 0; kc2 < 4; kc2++) {
            uint32_t ph[4], pl[4];
            {
                float r0, r1;
                ph[0] = pack_hi(sacc[2 * kc2][0],     sacc[2 * kc2][1],     r0, r1);
                pl[0] = pack_bf2(r0, r1);
                ph[1] = pack_hi(sacc[2 * kc2][2],     sacc[2 * kc2][3],     r0, r1);
                pl[1] = pack_bf2(r0, r1);
                ph[2] = pack_hi(sacc[2 * kc2 + 1][0], sacc[2 * kc2 + 1][1], r0, r1);
                pl[2] = pack_bf2(r0, r1);
                ph[3] = pack_hi(sacc[2 * kc2 + 1][2], sacc[2 * kc2 + 1][3], r0, r1);
                pl[3] = pack_bf2(r0, r1);
            }
            #pragma unroll
            for (int ds = 0; ds < 8; ds++) {
                uint32_t vh[4], vl[4];
                uint32_t aoff = ((kc2 * 16 + vrow) * AT_ROWP + ds * 16 + vcolx) * 2;
                ldsm4t(vh, sb + AT_V_OFF * 2 + aoff);
                ldsm4t(vl, sb + AT_VL_OFF * 2 + aoff);
                uint32_t b0h[2] = {vh[0], vh[1]}, b1h[2] = {vh[2], vh[3]};
                uint32_t b0l[2] = {vl[0], vl[1]}, b1l[2] = {vl[2], vl[3]};
                mma16816(po[2 * ds],     ph, b0h);
                mma16816(po[2 * ds],     pl, b0h);
                mma16816(po[2 * ds],     ph, b0l);
                mma16816(po[2 * ds + 1], ph, b1h);
                mma16816(po[2 * ds + 1], pl, b1h);
                mma16816(po[2 * ds + 1], ph, b1l);
            }
        }
    }

    // ---- epilogue: normalize, split hi/lo bf16, store ----
    float inv0 = 1.f / l0, inv1 = 1.f / l1;
    size_t tok0 = (size_t)(b * SEQT + q0 + wid * 16 + g);
    size_t tok1 = tok0 + 8;
    #pragma unroll
    for (int dj = 0; dj < 16; dj++) {
        int col = h * HD + dj * 8 + t * 2;
        float v0 = po[dj][0] * inv0, v1 = po[dj][1] * inv0;
        float v2 = po[dj][2] * inv1, v3 = po[dj][3] * inv1;
        float r0, r1, r2, r3;
        uint32_t h01 = pack_hi(v0, v1, r0, r1);
        uint32_t h23 = pack_hi(v2, v3, r2, r3);
        *(uint32_t*)(Oh + tok0 * DIM + col) = h01;
        *(uint32_t*)(Oh + tok1 * DIM + col) = h23;
        *(uint32_t*)(Ol + tok0 * DIM + col) = pack_bf2(r0, r1);
        *(uint32_t*)(Ol + tok1 * DIM + col) = pack_bf2(r2, r3);
    }
}

// ---------------------------------------------------------------------------
extern "C" void kernel_launch(void* const* d_in, const int* in_sizes, int n_in,
                              void* d_out, int out_size) {
    const float* enc = (const float*)d_in[0];
    const float* dec = (const float*)d_in[1];
    const float* Wkv = (const float*)d_in[2];
    const float* bkv = (const float*)d_in[3];
    const float* Wq  = (const float*)d_in[4];
    const float* bq  = (const float*)d_in[5];
    const float* Wo  = (const float*)d_in[6];
    const float* bo  = (const float*)d_in[7];
    float* out = (float*)d_out;

    __nv_bfloat16 *eh, *el, *dh, *dl, *kvh, *kvl, *qh, *ql, *aoh, *aol;
    __nv_bfloat16 *wkvh, *wkvl, *wqh, *wql, *woh, *wol;
    cudaGetSymbolAddress((void**)&eh,  g_enc_h);  cudaGetSymbolAddress((void**)&el,  g_enc_l);
    cudaGetSymbolAddress((void**)&dh,  g_dec_h);  cudaGetSymbolAddress((void**)&dl,  g_dec_l);
    cudaGetSymbolAddress((void**)&kvh, g_kv_h);   cudaGetSymbolAddress((void**)&kvl, g_kv_l);
    cudaGetSymbolAddress((void**)&qh,  g_q_h);    cudaGetSymbolAddress((void**)&ql,  g_q_l);
    cudaGetSymbolAddress((void**)&aoh, g_ao_h);   cudaGetSymbolAddress((void**)&aol, g_ao_l);
    cudaGetSymbolAddress((void**)&wkvh, g_wkv_h); cudaGetSymbolAddress((void**)&wkvl, g_wkv_l);
    cudaGetSymbolAddress((void**)&wqh, g_wq_h);   cudaGetSymbolAddress((void**)&wql, g_wq_l);
    cudaGetSymbolAddress((void**)&woh, g_wo_h);   cudaGetSymbolAddress((void**)&wol, g_wo_l);

    cudaFuncSetAttribute(gemm_tc, cudaFuncAttributeMaxDynamicSharedMemorySize, GT_SMEM);
    cudaFuncSetAttribute(attn_mma, cudaFuncAttributeMaxDynamicSharedMemorySize, AT_SMEM);

    int n4_act = (M_TOK * DIM) / 4;
    const float qscale = 0.08838834764831845f;   // 1/sqrt(128)

    split_kernel<<<(n4_act + 255) / 256, 256>>>(enc, eh, el, n4_act);
    split_kernel<<<(n4_act + 255) / 256, 256>>>(dec, dh, dl, n4_act);
    splitT_kernel<<<dim3(TWO_DIM / 32, DIM / 32), 256>>>(Wkv, wkvh, wkvl, DIM, TWO_DIM);
    splitT_kernel<<<dim3(DIM / 32,     DIM / 32), 256>>>(Wq,  wqh,  wql,  DIM, DIM);
    splitT_kernel<<<dim3(DIM / 32,     DIM / 32), 256>>>(Wo,  woh,  wol,  DIM, DIM);

    // KV projection -> bf16 hi/lo
    gemm_tc<<<dim3(TWO_DIM / 128, M_TOK / 128), 256, GT_SMEM>>>(
        eh, el, wkvh, wkvl, bkv, 1.0f, nullptr, kvh, kvl, 1, M_TOK, TWO_DIM, DIM);
    // Q projection -> bf16 hi/lo, pre-scaled by 1/sqrt(HD)
    gemm_tc<<<dim3(DIM / 128, M_TOK / 128), 256, GT_SMEM>>>(
        dh, dl, wqh, wql, bq, qscale, nullptr, qh, ql, 1, M_TOK, DIM, DIM);

    // attention -> bf16 hi/lo
    attn_mma<<<dim3(SEQT / 64, NH, BATCH), 128, AT_SMEM>>>(qh, ql, kvh, kvl, aoh, aol);

    // O projection -> fp32 out
    gemm_tc<<<dim3(DIM / 128, M_TOK / 128), 256, GT_SMEM>>>(
        aoh, aol, woh, wol, bo, 1.0f, out, nullptr, nullptr, 0, M_TOK, DIM, DIM);
}

// round 5
// speedup vs baseline: 5.3016x; 1.5973x over previous
#include <cuda_runtime.h>
#include <cuda_fp16.h>
#include <cstdint>
#include <math.h>

#define DIM     2048
#define TWO_DIM 4096
#define NH      16
#define HD      128
#define BATCH   4
#define SEQT    2048
#define M_TOK   8192   // BATCH*SEQT

// ---------------- scratch (__device__ globals: allocation-free rule) -------
__device__ __half g_enc_h[(size_t)M_TOK * DIM];
__device__ __half g_enc_l[(size_t)M_TOK * DIM];
__device__ __half g_dec_h[(size_t)M_TOK * DIM];
__device__ __half g_dec_l[(size_t)M_TOK * DIM];
__device__ __half g_kv   [(size_t)M_TOK * TWO_DIM];   // K|V single fp16
__device__ __half g_q_h  [(size_t)M_TOK * DIM];
__device__ __half g_q_l  [(size_t)M_TOK * DIM];
__device__ __half g_ao_h [(size_t)M_TOK * DIM];
__device__ __half g_ao_l [(size_t)M_TOK * DIM];
// weights transposed to [N, K], single fp16
__device__ __half g_wkv[(size_t)TWO_DIM * DIM];
__device__ __half g_wq [(size_t)DIM * DIM];
__device__ __half g_wo [(size_t)DIM * DIM];

// ---------------- helpers ---------------------------------------------------
__device__ __forceinline__ uint32_t smem_u32(const void* p) {
    uint32_t a;
    asm("{ .reg .u64 t; cvta.to.shared.u64 t, %1; cvt.u32.u64 %0, t; }" : "=r"(a) : "l"(p));
    return a;
}
__device__ __forceinline__ void cp_async16(uint32_t dst, const void* src) {
    asm volatile("cp.async.cg.shared.global [%0], [%1], 16;" :: "r"(dst), "l"(src));
}
#define CP_COMMIT() asm volatile("cp.async.commit_group;" ::: "memory")

__device__ __forceinline__ void mma16816(float* d, const uint32_t* a, const uint32_t* b) {
    asm volatile(
        "mma.sync.aligned.m16n8k16.row.col.f32.f16.f16.f32 "
        "{%0,%1,%2,%3}, {%4,%5,%6,%7}, {%8,%9}, {%0,%1,%2,%3};\n"
        : "+f"(d[0]), "+f"(d[1]), "+f"(d[2]), "+f"(d[3])
        : "r"(a[0]), "r"(a[1]), "r"(a[2]), "r"(a[3]), "r"(b[0]), "r"(b[1]));
}
__device__ __forceinline__ void ldsm4(uint32_t* r, uint32_t saddr) {
    asm volatile("ldmatrix.sync.aligned.m8n8.x4.shared.b16 {%0,%1,%2,%3}, [%4];"
        : "=r"(r[0]), "=r"(r[1]), "=r"(r[2]), "=r"(r[3]) : "r"(saddr));
}
__device__ __forceinline__ void ldsm4t(uint32_t* r, uint32_t saddr) {
    asm volatile("ldmatrix.sync.aligned.m8n8.x4.trans.shared.b16 {%0,%1,%2,%3}, [%4];"
        : "=r"(r[0]), "=r"(r[1]), "=r"(r[2]), "=r"(r[3]) : "r"(saddr));
}
__device__ __forceinline__ uint32_t pack_hi_h(float v0, float v1, float& r0, float& r1) {
    __half2 h = __floats2half2_rn(v0, v1);
    r0 = v0 - __half2float(__low2half(h));
    r1 = v1 - __half2float(__high2half(h));
    return *reinterpret_cast<uint32_t*>(&h);
}
__device__ __forceinline__ uint32_t pack_h2(float v0, float v1) {
    __half2 h = __floats2half2_rn(v0, v1);
    return *reinterpret_cast<uint32_t*>(&h);
}

// ---------------- conversion kernels ---------------------------------------
__global__ __launch_bounds__(256)
void split_kernel(const float* __restrict__ x, __half* __restrict__ h,
                  __half* __restrict__ l, int n4) {
    int i = blockIdx.x * blockDim.x + threadIdx.x;
    if (i >= n4) return;
    float4 v = ((const float4*)x)[i];
    __half h0 = __float2half_rn(v.x), h1 = __float2half_rn(v.y);
    __half h2 = __float2half_rn(v.z), h3 = __float2half_rn(v.w);
    __half l0 = __float2half_rn(v.x - __half2float(h0));
    __half l1 = __float2half_rn(v.y - __half2float(h1));
    __half l2 = __float2half_rn(v.z - __half2float(h2));
    __half l3 = __float2half_rn(v.w - __half2float(h3));
    ((__half2*)h)[2 * i]     = __halves2half2(h0, h1);
    ((__half2*)h)[2 * i + 1] = __halves2half2(h2, h3);
    ((__half2*)l)[2 * i]     = __halves2half2(l0, l1);
    ((__half2*)l)[2 * i + 1] = __halves2half2(l2, l3);
}

// W[K,N] fp32 -> WT [N,K] fp16 (single)
__global__ __launch_bounds__(256)
void roundT_kernel(const float* __restrict__ W, __half* __restrict__ h, int K, int N) {
    __shared__ float t[32][33];
    int n0 = blockIdx.x * 32, k0 = blockIdx.y * 32;
    int tx = threadIdx.x & 31, ty = threadIdx.x >> 5;
    #pragma unroll
    for (int i = 0; i < 32; i += 8)
        t[ty + i][tx] = W[(size_t)(k0 + ty + i) * N + n0 + tx];
    __syncthreads();
    #pragma unroll
    for (int i = 0; i < 32; i += 8)
        h[(size_t)(n0 + ty + i) * K + k0 + tx] = __float2half_rn(t[tx][ty + i]);
}

// ---------------- mma.sync 2-product fp16 GEMM ------------------------------
// C = (Ah+Al) @ Bt^T + bias.  Bt [N,K] single fp16.
// CTA 128x128, 8 warps (2m x 4n), warp 64x32.  BK=32, 2-stage cp.async.
// mode 0: fp32 out.  mode 1: scale*(acc+bias) -> half hi/lo.  mode 2: -> half.
#define BK        32
#define ROWQ      40
#define ARR_ELEMS (128 * ROWQ)            // 5120 halfs = 10240 B
#define STAGE_BYTES (3 * ARR_ELEMS * 2)   // Ah, Al, B = 30720
#define GT_SMEM   (2 * STAGE_BYTES)       // 61440

__device__ __forceinline__ void load_chunk(uint32_t sbase,
    const __half* Ah, const __half* Al, const __half* B, int K, int kt, int tid)
{
    #pragma unroll
    for (int i = 0; i < 2; i++) {
        int idx = i * 256 + tid;
        int r = idx >> 2, c = idx & 3;
        uint32_t doff = (uint32_t)(r * ROWQ + c * 8) * 2;
        size_t   soff = (size_t)r * K + kt + c * 8;
        cp_async16(sbase + doff,                     Ah + soff);
        cp_async16(sbase + ARR_ELEMS * 2 + doff,     Al + soff);
        cp_async16(sbase + ARR_ELEMS * 4 + doff,     B  + soff);
    }
}

__global__ __launch_bounds__(256)
void gemm_tc(const __half* __restrict__ Ah, const __half* __restrict__ Al,
             const __half* __restrict__ Bt,
             const float* __restrict__ bias, float scale,
             float* __restrict__ Cf,
             __half* __restrict__ Ch, __half* __restrict__ Cl,
             int mode, int M, int N, int K)
{
    extern __shared__ __align__(16) char sm_g[];
    uint32_t sbase = smem_u32(sm_g);
    int tid = threadIdx.x, wid = tid >> 5, lid = tid & 31;
    int g = lid >> 2, t = lid & 3;
    int wm = (wid & 1) * 64;
    int wn = (wid >> 1) * 32;
    int m0 = blockIdx.y * 128, n0 = blockIdx.x * 128;

    const __half* A_h = Ah + (size_t)m0 * K;
    const __half* A_l = Al + (size_t)m0 * K;
    const __half* B_p = Bt + (size_t)n0 * K;

    float acc[4][4][4];
    #pragma unroll
    for (int i = 0; i < 4; i++)
        #pragma unroll
        for (int j = 0; j < 4; j++)
            #pragma unroll
            for (int r = 0; r < 4; r++) acc[i][j][r] = 0.f;

    const int NCH = K / BK;

    load_chunk(sbase,               A_h, A_l, B_p, K, 0,  tid);
    CP_COMMIT();
    load_chunk(sbase + STAGE_BYTES, A_h, A_l, B_p, K, BK, tid);
    CP_COMMIT();

    // ldmatrix lane addressing
    int arow  = lid & 15;
    int akoff = ((lid >> 4) & 1) * 8;
    int brow  = ((lid >> 4) & 1) * 8 + (lid & 7);
    int bkoff = ((lid >> 3) & 1) * 8;

    for (int c = 0; c < NCH; c++) {
        int s = c & 1;
        if (c == NCH - 1) asm volatile("cp.async.wait_group 0;" ::: "memory");
        else              asm volatile("cp.async.wait_group 1;" ::: "memory");
        __syncthreads();

        uint32_t stb = sbase + (uint32_t)s * STAGE_BYTES;
        uint32_t aAh = stb;
        uint32_t aAl = stb + ARR_ELEMS * 2;
        uint32_t aB  = stb + ARR_ELEMS * 4;

        #pragma unroll
        for (int ks = 0; ks < BK; ks += 16) {
            uint32_t ah[4][4], al[4][4], bb[2][4];
            #pragma unroll
            for (int mi = 0; mi < 4; mi++) {
                uint32_t off = (uint32_t)((wm + mi * 16 + arow) * ROWQ + ks + akoff) * 2;
                ldsm4(ah[mi], aAh + off);
                ldsm4(al[mi], aAl + off);
            }
            #pragma unroll
            for (int p = 0; p < 2; p++) {
                uint32_t off = (uint32_t)((wn + p * 16 + brow) * ROWQ + ks + bkoff) * 2;
                ldsm4(bb[p], aB + off);
            }
            #pragma unroll
            for (int mi = 0; mi < 4; mi++)
                #pragma unroll
                for (int p = 0; p < 2; p++)
                    #pragma unroll
                    for (int h2 = 0; h2 < 2; h2++) {
                        mma16816(acc[mi][2 * p + h2], ah[mi], &bb[p][2 * h2]);
                        mma16816(acc[mi][2 * p + h2], al[mi], &bb[p][2 * h2]);
                    }
        }
        __syncthreads();

        if (c + 2 < NCH) {
            load_chunk(sbase + (uint32_t)s * STAGE_BYTES,
                       A_h, A_l, B_p, K, (c + 2) * BK, tid);
            CP_COMMIT();
        }
    }

    #pragma unroll
    for (int nj = 0; nj < 4; nj++) {
        int col = n0 + wn + nj * 8 + t * 2;
        float b0 = bias[col], b1 = bias[col + 1];
        #pragma unroll
        for (int mi = 0; mi < 4; mi++) {
            int row = m0 + wm + mi * 16 + g;
            float v0 = acc[mi][nj][0] + b0, v1 = acc[mi][nj][1] + b1;
            float v2 = acc[mi][nj][2] + b0, v3 = acc[mi][nj][3] + b1;
            if (mode == 0) {
                *(float2*)(Cf + (size_t)row * N + col)       = make_float2(v0, v1);
                *(float2*)(Cf + (size_t)(row + 8) * N + col) = make_float2(v2, v3);
            } else if (mode == 2) {
                *(uint32_t*)(Ch + (size_t)row * N + col)       = pack_h2(v0, v1);
                *(uint32_t*)(Ch + (size_t)(row + 8) * N + col) = pack_h2(v2, v3);
            } else {
                v0 *= scale; v1 *= scale; v2 *= scale; v3 *= scale;
                float r0, r1, r2, r3;
                uint32_t h01 = pack_hi_h(v0, v1, r0, r1);
                uint32_t h23 = pack_hi_h(v2, v3, r2, r3);
                *(uint32_t*)(Ch + (size_t)row * N + col)       = h01;
                *(uint32_t*)(Ch + (size_t)(row + 8) * N + col) = h23;
                *(uint32_t*)(Cl + (size_t)row * N + col)       = pack_h2(r0, r1);
                *(uint32_t*)(Cl + (size_t)(row + 8) * N + col) = pack_h2(r2, r3);
            }
        }
    }
}

// ---------------- 2-product fp16 flash attention ----------------------------
// CTA: 64 q rows, 4 warps x 16 rows, 64 keys/iter, double-buffered K/V.
#define AT_ROWP 136
#define AT_TILE (64 * AT_ROWP)            // elems
#define AT_Q_OFF   0
#define AT_QL_OFF  (AT_TILE)
#define AT_K_OFF(s)  ((2 + 2 * (s)) * AT_TILE)
#define AT_V_OFF(s)  ((3 + 2 * (s)) * AT_TILE)
#define AT_SMEM    (6 * AT_TILE * 2)      // 104448 B

__device__ __forceinline__ void at_load_kv(uint32_t sb, const __half* KV,
                                           int b, int h, int kb, int s, int tid)
{
    const __half* src = KV + (size_t)(b * SEQT + kb * 64) * TWO_DIM + h * HD;
    #pragma unroll
    for (int i = 0; i < 8; i++) {
        int idx = i * 128 + tid;
        int r = idx >> 4, seg = idx & 15;
        uint32_t doff = (uint32_t)(r * AT_ROWP + seg * 8) * 2;
        size_t goff = (size_t)r * TWO_DIM + seg * 8;
        cp_async16(sb + AT_K_OFF(s) * 2 + doff, src + goff);
        cp_async16(sb + AT_V_OFF(s) * 2 + doff, src + DIM + goff);
    }
}

__global__ __launch_bounds__(128)
void attn_mma(const __half* __restrict__ Qh, const __half* __restrict__ Ql,
              const __half* __restrict__ KV,
              __half* __restrict__ Oh, __half* __restrict__ Ol)
{
    extern __shared__ __align__(16) char sab[];
    uint32_t sb = smem_u32(sab);
    int tid = threadIdx.x, wid = tid >> 5, lid = tid & 31;
    int g = lid >> 2, t = lid & 3;
    int qb = blockIdx.x, h = blockIdx.y, b = blockIdx.z;
    int q0 = qb * 64;

    // Q tile (pre-scaled hi/lo)
    {
        const __half* srcH = Qh + (size_t)(b * SEQT + q0) * DIM + h * HD;
        const __half* srcL = Ql + (size_t)(b * SEQT + q0) * DIM + h * HD;
        #pragma unroll
        for (int i = 0; i < 8; i++) {
            int idx = i * 128 + tid;
            int r = idx >> 4, seg = idx & 15;
            uint32_t doff = (uint32_t)(r * AT_ROWP + seg * 8) * 2;
            size_t goff = (size_t)r * DIM + seg * 8;
            cp_async16(sb + AT_Q_OFF * 2 + doff,  srcH + goff);
            cp_async16(sb + AT_QL_OFF * 2 + doff, srcL + goff);
        }
        CP_COMMIT();
    }
    at_load_kv(sb, KV, b, h, 0, 0, tid);
    CP_COMMIT();

    float m0 = -1e30f, m1 = -1e30f, l0 = 0.f, l1 = 0.f;
    float po[16][4];
    #pragma unroll
    for (int i = 0; i < 16; i++)
        #pragma unroll
        for (int r = 0; r < 4; r++) po[i][r] = 0.f;

    // ldmatrix lane addressing
    int qrow  = lid & 15;
    int qkoff = ((lid >> 4) & 1) * 8;
    int krow  = ((lid >> 4) & 1) * 8 + (lid & 7);
    int kkoff = ((lid >> 3) & 1) * 8;
    uint32_t vrow  = (uint32_t)(lid & 15);
    uint32_t vcolx = (lid & 16) ? 8u : 0u;

    for (int kb = 0; kb <= qb; kb++) {
        int s = kb & 1;
        if (kb < qb) { at_load_kv(sb, KV, b, h, kb + 1, s ^ 1, tid); CP_COMMIT(); }
        if (kb < qb) asm volatile("cp.async.wait_group 1;" ::: "memory");
        else         asm volatile("cp.async.wait_group 0;" ::: "memory");
        __syncthreads();

        uint32_t aQh = sb + AT_Q_OFF * 2;
        uint32_t aQl = sb + AT_QL_OFF * 2;
        uint32_t aK  = sb + AT_K_OFF(s) * 2;
        uint32_t aV  = sb + AT_V_OFF(s) * 2;

        // ---- S = (Qh+Ql) @ K^T ----
        float sacc[8][4];
        #pragma unroll
        for (int nj = 0; nj < 8; nj++)
            #pragma unroll
            for (int r = 0; r < 4; r++) sacc[nj][r] = 0.f;

        #pragma unroll
        for (int kc = 0; kc < 8; kc++) {
            uint32_t ah[4], al[4];
            uint32_t qoff = (uint32_t)((wid * 16 + qrow) * AT_ROWP + kc * 16 + qkoff) * 2;
            ldsm4(ah, aQh + qoff);
            ldsm4(al, aQl + qoff);
            #pragma unroll
            for (int p = 0; p < 4; p++) {
                uint32_t kf[4];
                uint32_t koff = (uint32_t)((p * 16 + krow) * AT_ROWP + kc * 16 + kkoff) * 2;
                ldsm4(kf, aK + koff);
                #pragma unroll
                for (int h2 = 0; h2 < 2; h2++) {
                    mma16816(sacc[2 * p + h2], ah, &kf[2 * h2]);
                    mma16816(sacc[2 * p + h2], al, &kf[2 * h2]);
                }
            }
        }

        // ---- causal mask (diagonal block only) ----
        int ig0 = q0 + wid * 16 + g;
        int ig1 = ig0 + 8;
        if (kb == qb) {
            #pragma unroll
            for (int nj = 0; nj < 8; nj++) {
                int c0 = kb * 64 + nj * 8 + t * 2;
                if (c0     > ig0) sacc[nj][0] = -1e30f;
                if (c0 + 1 > ig0) sacc[nj][1] = -1e30f;
                if (c0     > ig1) sacc[nj][2] = -1e30f;
                if (c0 + 1 > ig1) sacc[nj][3] = -1e30f;
            }
        }

        // ---- online softmax ----
        float rmax0 = -1e30f, rmax1 = -1e30f;
        #pragma unroll
        for (int nj = 0; nj < 8; nj++) {
            rmax0 = fmaxf(rmax0, fmaxf(sacc[nj][0], sacc[nj][1]));
            rmax1 = fmaxf(rmax1, fmaxf(sacc[nj][2], sacc[nj][3]));
        }
        rmax0 = fmaxf(rmax0, __shfl_xor_sync(0xffffffffu, rmax0, 1));
        rmax0 = fmaxf(rmax0, __shfl_xor_sync(0xffffffffu, rmax0, 2));
        rmax1 = fmaxf(rmax1, __shfl_xor_sync(0xffffffffu, rmax1, 1));
        rmax1 = fmaxf(rmax1, __shfl_xor_sync(0xffffffffu, rmax1, 2));
        float mn0 = fmaxf(m0, rmax0), mn1 = fmaxf(m1, rmax1);
        float alpha0 = __expf(m0 - mn0), alpha1 = __expf(m1 - mn1);
        float rs0 = 0.f, rs1 = 0.f;
        #pragma unroll
        for (int nj = 0; nj < 8; nj++) {
            float p0 = __expf(sacc[nj][0] - mn0);
            float p1 = __expf(sacc[nj][1] - mn0);
            float p2 = __expf(sacc[nj][2] - mn1);
            float p3 = __expf(sacc[nj][3] - mn1);
            sacc[nj][0] = p0; sacc[nj][1] = p1; sacc[nj][2] = p2; sacc[nj][3] = p3;
            rs0 += p0 + p1;
            rs1 += p2 + p3;
        }
        rs0 += __shfl_xor_sync(0xffffffffu, rs0, 1);
        rs0 += __shfl_xor_sync(0xffffffffu, rs0, 2);
        rs1 += __shfl_xor_sync(0xffffffffu, rs1, 1);
        rs1 += __shfl_xor_sync(0xffffffffu, rs1, 2);
        l0 = l0 * alpha0 + rs0;
        l1 = l1 * alpha1 + rs1;
        m0 = mn0; m1 = mn1;

        #pragma unroll
        for (int dj = 0; dj < 16; dj++) {
            po[dj][0] *= alpha0; po[dj][1] *= alpha0;
            po[dj][2] *= alpha1; po[dj][3] *= alpha1;
        }

        // ---- O += (Ph+Pl) @ V ----
        #pragma unroll
        for (int kc2 = 0; kc2 < 4; kc2++) {
            uint32_t ph[4], pl[4];
            {
                float r0, r1;
                ph[0] = pack_hi_h(sacc[2 * kc2][0],     sacc[2 * kc2][1],     r0, r1);
                pl[0] = pack_h2(r0, r1);
                ph[1] = pack_hi_h(sacc[2 * kc2][2],     sacc[2 * kc2][3],     r0, r1);
                pl[1] = pack_h2(r0, r1);
                ph[2] = pack_hi_h(sacc[2 * kc2 + 1][0], sacc[2 * kc2 + 1][1], r0, r1);
                pl[2] = pack_h2(r0, r1);
                ph[3] = pack_hi_h(sacc[2 * kc2 + 1][2], sacc[2 * kc2 + 1][3], r0, r1);
                pl[3] = pack_h2(r0, r1);
            }
            #pragma unroll
            for (int ds = 0; ds < 8; ds++) {
                uint32_t vh[4];
                uint32_t aoff = ((kc2 * 16 + vrow) * AT_ROWP + ds * 16 + vcolx) * 2;
                ldsm4t(vh, aV + aoff);
                mma16816(po[2 * ds],     ph, &vh[0]);
                mma16816(po[2 * ds],     pl, &vh[0]);
                mma16816(po[2 * ds + 1], ph, &vh[2]);
                mma16816(po[2 * ds + 1], pl, &vh[2]);
            }
        }
        __syncthreads();   // stage s fully consumed before next-next load
    }

    // ---- epilogue: normalize, split hi/lo fp16, store ----
    float inv0 = 1.f / l0, inv1 = 1.f / l1;
    size_t tok0 = (size_t)(b * SEQT + q0 + wid * 16 + g);
    size_t tok1 = tok0 + 8;
    #pragma unroll
    for (int dj = 0; dj < 16; dj++) {
        int col = h * HD + dj * 8 + t * 2;
        float v0 = po[dj][0] * inv0, v1 = po[dj][1] * inv0;
        float v2 = po[dj][2] * inv1, v3 = po[dj][3] * inv1;
        float r0, r1, r2, r3;
        uint32_t h01 = pack_hi_h(v0, v1, r0, r1);
        uint32_t h23 = pack_hi_h(v2, v3, r2, r3);
        *(uint32_t*)(Oh + tok0 * DIM + col) = h01;
        *(uint32_t*)(Oh + tok1 * DIM + col) = h23;
        *(uint32_t*)(Ol + tok0 * DIM + col) = pack_h2(r0, r1);
        *(uint32_t*)(Ol + tok1 * DIM + col) = pack_h2(r2, r3);
    }
}

// ---------------------------------------------------------------------------
extern "C" void kernel_launch(void* const* d_in, const int* in_sizes, int n_in,
                              void* d_out, int out_size) {
    const float* enc = (const float*)d_in[0];
    const float* dec = (const float*)d_in[1];
    const float* Wkv = (const float*)d_in[2];
    const float* bkv = (const float*)d_in[3];
    const float* Wq  = (const float*)d_in[4];
    const float* bq  = (const float*)d_in[5];
    const float* Wo  = (const float*)d_in[6];
    const float* bo  = (const float*)d_in[7];
    float* out = (float*)d_out;

    __half *eh, *el, *dh, *dl, *kv, *qh, *ql, *aoh, *aol, *wkv, *wq, *wo;
    cudaGetSymbolAddress((void**)&eh,  g_enc_h);  cudaGetSymbolAddress((void**)&el,  g_enc_l);
    cudaGetSymbolAddress((void**)&dh,  g_dec_h);  cudaGetSymbolAddress((void**)&dl,  g_dec_l);
    cudaGetSymbolAddress((void**)&kv,  g_kv);
    cudaGetSymbolAddress((void**)&qh,  g_q_h);    cudaGetSymbolAddress((void**)&ql,  g_q_l);
    cudaGetSymbolAddress((void**)&aoh, g_ao_h);   cudaGetSymbolAddress((void**)&aol, g_ao_l);
    cudaGetSymbolAddress((void**)&wkv, g_wkv);
    cudaGetSymbolAddress((void**)&wq,  g_wq);
    cudaGetSymbolAddress((void**)&wo,  g_wo);

    cudaFuncSetAttribute(gemm_tc, cudaFuncAttributeMaxDynamicSharedMemorySize, GT_SMEM);
    cudaFuncSetAttribute(attn_mma, cudaFuncAttributeMaxDynamicSharedMemorySize, AT_SMEM);

    int n4_act = (M_TOK * DIM) / 4;
    const float qscale = 0.08838834764831845f;   // 1/sqrt(128)

    split_kernel<<<(n4_act + 255) / 256, 256>>>(enc, eh, el, n4_act);
    split_kernel<<<(n4_act + 255) / 256, 256>>>(dec, dh, dl, n4_act);
    roundT_kernel<<<dim3(TWO_DIM / 32, DIM / 32), 256>>>(Wkv, wkv, DIM, TWO_DIM);
    roundT_kernel<<<dim3(DIM / 32,     DIM / 32), 256>>>(Wq,  wq,  DIM, DIM);
    roundT_kernel<<<dim3(DIM / 32,     DIM / 32), 256>>>(Wo,  wo,  DIM, DIM);

    // KV projection -> single fp16 (mode 2)
    gemm_tc<<<dim3(TWO_DIM / 128, M_TOK / 128), 256, GT_SMEM>>>(
        eh, el, wkv, bkv, 1.0f, nullptr, kv, nullptr, 2, M_TOK, TWO_DIM, DIM);
    // Q projection -> fp16 hi/lo, pre-scaled (mode 1)
    gemm_tc<<<dim3(DIM / 128, M_TOK / 128), 256, GT_SMEM>>>(
        dh, dl, wq, bq, qscale, nullptr, qh, ql, 1, M_TOK, DIM, DIM);

    // attention -> fp16 hi/lo
    attn_mma<<<dim3(SEQT / 64, NH, BATCH), 128, AT_SMEM>>>(qh, ql, kv, aoh, aol);

    // O projection -> fp32 out (mode 0)
    gemm_tc<<<dim3(DIM / 128, M_TOK / 128), 256, GT_SMEM>>>(
        aoh, aol, wo, bo, 1.0f, out, nullptr, nullptr, 0, M_TOK, DIM, DIM);
}

// round 6
// speedup vs baseline: 5.4655x; 1.0309x over previous
#include <cuda_runtime.h>
#include <cuda_fp16.h>
#include <cstdint>
#include <math.h>

#define DIM     2048
#define TWO_DIM 4096
#define NH      16
#define HD      128
#define BATCH   4
#define SEQT    2048
#define M_TOK   8192   // BATCH*SEQT

// ---------------- scratch (__device__ globals: allocation-free rule) -------
__device__ __half g_enc_h[(size_t)M_TOK * DIM];
__device__ __half g_enc_l[(size_t)M_TOK * DIM];
__device__ __half g_dec_h[(size_t)M_TOK * DIM];
__device__ __half g_dec_l[(size_t)M_TOK * DIM];
__device__ __half g_kv   [(size_t)M_TOK * TWO_DIM];   // K|V single fp16
__device__ __half g_q_h  [(size_t)M_TOK * DIM];
__device__ __half g_q_l  [(size_t)M_TOK * DIM];
__device__ __half g_ao_h [(size_t)M_TOK * DIM];
__device__ __half g_ao_l [(size_t)M_TOK * DIM];
// weights transposed to [N, K], single fp16
__device__ __half g_wkv[(size_t)TWO_DIM * DIM];
__device__ __half g_wq [(size_t)DIM * DIM];
__device__ __half g_wo [(size_t)DIM * DIM];

// ---------------- helpers ---------------------------------------------------
__device__ __forceinline__ uint32_t smem_u32(const void* p) {
    uint32_t a;
    asm("{ .reg .u64 t; cvta.to.shared.u64 t, %1; cvt.u32.u64 %0, t; }" : "=r"(a) : "l"(p));
    return a;
}
__device__ __forceinline__ void cp_async16(uint32_t dst, const void* src) {
    asm volatile("cp.async.cg.shared.global [%0], [%1], 16;" :: "r"(dst), "l"(src));
}
#define CP_COMMIT() asm volatile("cp.async.commit_group;" ::: "memory")

__device__ __forceinline__ void mma16816(float* d, const uint32_t* a, const uint32_t* b) {
    asm volatile(
        "mma.sync.aligned.m16n8k16.row.col.f32.f16.f16.f32 "
        "{%0,%1,%2,%3}, {%4,%5,%6,%7}, {%8,%9}, {%0,%1,%2,%3};\n"
        : "+f"(d[0]), "+f"(d[1]), "+f"(d[2]), "+f"(d[3])
        : "r"(a[0]), "r"(a[1]), "r"(a[2]), "r"(a[3]), "r"(b[0]), "r"(b[1]));
}
__device__ __forceinline__ void ldsm4(uint32_t* r, uint32_t saddr) {
    asm volatile("ldmatrix.sync.aligned.m8n8.x4.shared.b16 {%0,%1,%2,%3}, [%4];"
        : "=r"(r[0]), "=r"(r[1]), "=r"(r[2]), "=r"(r[3]) : "r"(saddr));
}
__device__ __forceinline__ void ldsm4t(uint32_t* r, uint32_t saddr) {
    asm volatile("ldmatrix.sync.aligned.m8n8.x4.trans.shared.b16 {%0,%1,%2,%3}, [%4];"
        : "=r"(r[0]), "=r"(r[1]), "=r"(r[2]), "=r"(r[3]) : "r"(saddr));
}
__device__ __forceinline__ uint32_t pack_hi_h(float v0, float v1, float& r0, float& r1) {
    __half2 h = __floats2half2_rn(v0, v1);
    r0 = v0 - __half2float(__low2half(h));
    r1 = v1 - __half2float(__high2half(h));
    return *reinterpret_cast<uint32_t*>(&h);
}
__device__ __forceinline__ uint32_t pack_h2(float v0, float v1) {
    __half2 h = __floats2half2_rn(v0, v1);
    return *reinterpret_cast<uint32_t*>(&h);
}

// ---------------- conversion kernels ---------------------------------------
__global__ __launch_bounds__(256)
void split_kernel(const float* __restrict__ x, __half* __restrict__ h,
                  __half* __restrict__ l, int n4) {
    int i = blockIdx.x * blockDim.x + threadIdx.x;
    if (i >= n4) return;
    float4 v = ((const float4*)x)[i];
    __half h0 = __float2half_rn(v.x), h1 = __float2half_rn(v.y);
    __half h2 = __float2half_rn(v.z), h3 = __float2half_rn(v.w);
    __half l0 = __float2half_rn(v.x - __half2float(h0));
    __half l1 = __float2half_rn(v.y - __half2float(h1));
    __half l2 = __float2half_rn(v.z - __half2float(h2));
    __half l3 = __float2half_rn(v.w - __half2float(h3));
    ((__half2*)h)[2 * i]     = __halves2half2(h0, h1);
    ((__half2*)h)[2 * i + 1] = __halves2half2(h2, h3);
    ((__half2*)l)[2 * i]     = __halves2half2(l0, l1);
    ((__half2*)l)[2 * i + 1] = __halves2half2(l2, l3);
}

// W[K,N] fp32 -> WT [N,K] fp16 (single)
__global__ __launch_bounds__(256)
void roundT_kernel(const float* __restrict__ W, __half* __restrict__ h, int K, int N) {
    __shared__ float t[32][33];
    int n0 = blockIdx.x * 32, k0 = blockIdx.y * 32;
    int tx = threadIdx.x & 31, ty = threadIdx.x >> 5;
    #pragma unroll
    for (int i = 0; i < 32; i += 8)
        t[ty + i][tx] = W[(size_t)(k0 + ty + i) * N + n0 + tx];
    __syncthreads();
    #pragma unroll
    for (int i = 0; i < 32; i += 8)
        h[(size_t)(n0 + ty + i) * K + k0 + tx] = __float2half_rn(t[tx][ty + i]);
}

// ---------------- mma.sync 2-product fp16 GEMM ------------------------------
// C = (Ah+Al) @ Bt^T + bias.  Bt [N,K] single fp16.
// CTA 128x128, 8 warps (2m x 4n), warp 64x32.  BK=32, 3-stage single-sync pipe.
#define BK        32
#define ROWQ      40
#define ARR_ELEMS (128 * ROWQ)            // 5120 halfs = 10240 B
#define STAGE_BYTES (3 * ARR_ELEMS * 2)   // Ah, Al, B = 30720
#define GT_STAGES 3
#define GT_SMEM   (GT_STAGES * STAGE_BYTES)   // 92160

__device__ __forceinline__ void load_chunk(uint32_t sbase,
    const __half* Ah, const __half* Al, const __half* B, int K, int kt, int tid)
{
    #pragma unroll
    for (int i = 0; i < 2; i++) {
        int idx = i * 256 + tid;
        int r = idx >> 2, c = idx & 3;
        uint32_t doff = (uint32_t)(r * ROWQ + c * 8) * 2;
        size_t   soff = (size_t)r * K + kt + c * 8;
        cp_async16(sbase + doff,                     Ah + soff);
        cp_async16(sbase + ARR_ELEMS * 2 + doff,     Al + soff);
        cp_async16(sbase + ARR_ELEMS * 4 + doff,     B  + soff);
    }
}

__global__ __launch_bounds__(256)
void gemm_tc(const __half* __restrict__ Ah, const __half* __restrict__ Al,
             const __half* __restrict__ Bt,
             const float* __restrict__ bias, float scale,
             float* __restrict__ Cf,
             __half* __restrict__ Ch, __half* __restrict__ Cl,
             int mode, int M, int N, int K)
{
    extern __shared__ __align__(16) char sm_g[];
    uint32_t sbase = smem_u32(sm_g);
    int tid = threadIdx.x, wid = tid >> 5, lid = tid & 31;
    int g = lid >> 2, t = lid & 3;
    int wm = (wid & 1) * 64;
    int wn = (wid >> 1) * 32;
    int m0 = blockIdx.y * 128, n0 = blockIdx.x * 128;

    const __half* A_h = Ah + (size_t)m0 * K;
    const __half* A_l = Al + (size_t)m0 * K;
    const __half* B_p = Bt + (size_t)n0 * K;

    float acc[4][4][4];
    #pragma unroll
    for (int i = 0; i < 4; i++)
        #pragma unroll
        for (int j = 0; j < 4; j++)
            #pragma unroll
            for (int r = 0; r < 4; r++) acc[i][j][r] = 0.f;

    const int NCH = K / BK;

    load_chunk(sbase,               A_h, A_l, B_p, K, 0,  tid);
    CP_COMMIT();
    load_chunk(sbase + STAGE_BYTES, A_h, A_l, B_p, K, BK, tid);
    CP_COMMIT();

    // ldmatrix lane addressing
    int arow  = lid & 15;
    int akoff = ((lid >> 4) & 1) * 8;
    int brow  = ((lid >> 4) & 1) * 8 + (lid & 7);
    int bkoff = ((lid >> 3) & 1) * 8;

    int ld_stage = 2;   // next stage to fill (chunk c+2 -> stage (c+2)%3)
    for (int c = 0; c < NCH; c++) {
        if (c == NCH - 1) asm volatile("cp.async.wait_group 0;" ::: "memory");
        else              asm volatile("cp.async.wait_group 1;" ::: "memory");
        __syncthreads();   // all warps done with stage (c-1)%3 -> safe to refill

        if (c + 2 < NCH) {
            load_chunk(sbase + (uint32_t)ld_stage * STAGE_BYTES,
                       A_h, A_l, B_p, K, (c + 2) * BK, tid);
            CP_COMMIT();
            ld_stage = (ld_stage + 1 == GT_STAGES) ? 0 : ld_stage + 1;
        }

        uint32_t stb = sbase + (uint32_t)(c % GT_STAGES) * STAGE_BYTES;
        uint32_t aAh = stb;
        uint32_t aAl = stb + ARR_ELEMS * 2;
        uint32_t aB  = stb + ARR_ELEMS * 4;

        #pragma unroll
        for (int ks = 0; ks < BK; ks += 16) {
            uint32_t ah[4][4], al[4][4], bb[2][4];
            #pragma unroll
            for (int mi = 0; mi < 4; mi++) {
                uint32_t off = (uint32_t)((wm + mi * 16 + arow) * ROWQ + ks + akoff) * 2;
                ldsm4(ah[mi], aAh + off);
                ldsm4(al[mi], aAl + off);
            }
            #pragma unroll
            for (int p = 0; p < 2; p++) {
                uint32_t off = (uint32_t)((wn + p * 16 + brow) * ROWQ + ks + bkoff) * 2;
                ldsm4(bb[p], aB + off);
            }
            #pragma unroll
            for (int mi = 0; mi < 4; mi++)
                #pragma unroll
                for (int p = 0; p < 2; p++)
                    #pragma unroll
                    for (int h2 = 0; h2 < 2; h2++) {
                        mma16816(acc[mi][2 * p + h2], ah[mi], &bb[p][2 * h2]);
                        mma16816(acc[mi][2 * p + h2], al[mi], &bb[p][2 * h2]);
                    }
        }
    }

    #pragma unroll
    for (int nj = 0; nj < 4; nj++) {
        int col = n0 + wn + nj * 8 + t * 2;
        float b0 = bias[col], b1 = bias[col + 1];
        #pragma unroll
        for (int mi = 0; mi < 4; mi++) {
            int row = m0 + wm + mi * 16 + g;
            float v0 = acc[mi][nj][0] + b0, v1 = acc[mi][nj][1] + b1;
            float v2 = acc[mi][nj][2] + b0, v3 = acc[mi][nj][3] + b1;
            if (mode == 0) {
                *(float2*)(Cf + (size_t)row * N + col)       = make_float2(v0, v1);
                *(float2*)(Cf + (size_t)(row + 8) * N + col) = make_float2(v2, v3);
            } else if (mode == 2) {
                *(uint32_t*)(Ch + (size_t)row * N + col)       = pack_h2(v0, v1);
                *(uint32_t*)(Ch + (size_t)(row + 8) * N + col) = pack_h2(v2, v3);
            } else {
                v0 *= scale; v1 *= scale; v2 *= scale; v3 *= scale;
                float r0, r1, r2, r3;
                uint32_t h01 = pack_hi_h(v0, v1, r0, r1);
                uint32_t h23 = pack_hi_h(v2, v3, r2, r3);
                *(uint32_t*)(Ch + (size_t)row * N + col)       = h01;
                *(uint32_t*)(Ch + (size_t)(row + 8) * N + col) = h23;
                *(uint32_t*)(Cl + (size_t)row * N + col)       = pack_h2(r0, r1);
                *(uint32_t*)(Cl + (size_t)(row + 8) * N + col) = pack_h2(r2, r3);
            }
        }
    }
}

// ---------------- 2-product fp16 flash attention ----------------------------
// CTA: 128 q rows, 8 warps x 16 rows, 64 keys/iter, double-buffered K/V,
// single __syncthreads per iteration.
#define AT_ROWP 136
#define AT_QTILE (128 * AT_ROWP)
#define AT_KTILE (64 * AT_ROWP)
#define AT_Q_OFF   0
#define AT_QL_OFF  AT_QTILE
#define AT_K_OFF(s)  (2 * AT_QTILE + 2 * (s) * AT_KTILE)
#define AT_V_OFF(s)  (AT_K_OFF(s) + AT_KTILE)
#define AT_SMEM    ((2 * AT_QTILE + 4 * AT_KTILE) * 2)   // 139264 B

__device__ __forceinline__ void at_load_kv(uint32_t sb, const __half* KV,
                                           int b, int h, int kb, int s, int tid)
{
    const __half* src = KV + (size_t)(b * SEQT + kb * 64) * TWO_DIM + h * HD;
    #pragma unroll
    for (int i = 0; i < 4; i++) {
        int idx = i * 256 + tid;
        int r = idx >> 4, seg = idx & 15;
        uint32_t doff = (uint32_t)(r * AT_ROWP + seg * 8) * 2;
        size_t goff = (size_t)r * TWO_DIM + seg * 8;
        cp_async16(sb + AT_K_OFF(s) * 2 + doff, src + goff);
        cp_async16(sb + AT_V_OFF(s) * 2 + doff, src + DIM + goff);
    }
}

__global__ __launch_bounds__(256)
void attn_mma(const __half* __restrict__ Qh, const __half* __restrict__ Ql,
              const __half* __restrict__ KV,
              __half* __restrict__ Oh, __half* __restrict__ Ol)
{
    extern __shared__ __align__(16) char sab[];
    uint32_t sb = smem_u32(sab);
    int tid = threadIdx.x, wid = tid >> 5, lid = tid & 31;
    int g = lid >> 2, t = lid & 3;
    int qb = blockIdx.x, h = blockIdx.y, b = blockIdx.z;
    int q0 = qb * 128;

    // Q tile (pre-scaled hi/lo): 128 rows
    {
        const __half* srcH = Qh + (size_t)(b * SEQT + q0) * DIM + h * HD;
        const __half* srcL = Ql + (size_t)(b * SEQT + q0) * DIM + h * HD;
        #pragma unroll
        for (int i = 0; i < 8; i++) {
            int idx = i * 256 + tid;
            int r = idx >> 4, seg = idx & 15;
            uint32_t doff = (uint32_t)(r * AT_ROWP + seg * 8) * 2;
            size_t goff = (size_t)r * DIM + seg * 8;
            cp_async16(sb + AT_Q_OFF * 2 + doff,  srcH + goff);
            cp_async16(sb + AT_QL_OFF * 2 + doff, srcL + goff);
        }
        CP_COMMIT();
    }
    at_load_kv(sb, KV, b, h, 0, 0, tid);
    CP_COMMIT();

    float m0 = -1e30f, m1 = -1e30f, l0 = 0.f, l1 = 0.f;
    float po[16][4];
    #pragma unroll
    for (int i = 0; i < 16; i++)
        #pragma unroll
        for (int r = 0; r < 4; r++) po[i][r] = 0.f;

    // ldmatrix lane addressing
    int qrow  = lid & 15;
    int qkoff = ((lid >> 4) & 1) * 8;
    int krow  = ((lid >> 4) & 1) * 8 + (lid & 7);
    int kkoff = ((lid >> 3) & 1) * 8;
    uint32_t vrow  = (uint32_t)(lid & 15);
    uint32_t vcolx = (lid & 16) ? 8u : 0u;

    int nkb = 2 * qb + 2;   // k blocks 0 .. 2qb+1 cover rows <= q0+127
    for (int kb = 0; kb < nkb; kb++) {
        int s = kb & 1;
        asm volatile("cp.async.wait_group 0;" ::: "memory");
        __syncthreads();   // all warps done with stage s (from iter kb-2)

        if (kb + 1 < nkb) { at_load_kv(sb, KV, b, h, kb + 1, s ^ 1, tid); CP_COMMIT(); }

        uint32_t aQh = sb + AT_Q_OFF * 2;
        uint32_t aQl = sb + AT_QL_OFF * 2;
        uint32_t aK  = sb + AT_K_OFF(s) * 2;
        uint32_t aV  = sb + AT_V_OFF(s) * 2;

        // ---- S = (Qh+Ql) @ K^T ----
        float sacc[8][4];
        #pragma unroll
        for (int nj = 0; nj < 8; nj++)
            #pragma unroll
            for (int r = 0; r < 4; r++) sacc[nj][r] = 0.f;

        #pragma unroll
        for (int kc = 0; kc < 8; kc++) {
            uint32_t ah[4], al[4];
            uint32_t qoff = (uint32_t)((wid * 16 + qrow) * AT_ROWP + kc * 16 + qkoff) * 2;
            ldsm4(ah, aQh + qoff);
            ldsm4(al, aQl + qoff);
            #pragma unroll
            for (int p = 0; p < 4; p++) {
                uint32_t kf[4];
                uint32_t koff = (uint32_t)((p * 16 + krow) * AT_ROWP + kc * 16 + kkoff) * 2;
                ldsm4(kf, aK + koff);
                #pragma unroll
                for (int h2 = 0; h2 < 2; h2++) {
                    mma16816(sacc[2 * p + h2], ah, &kf[2 * h2]);
                    mma16816(sacc[2 * p + h2], al, &kf[2 * h2]);
                }
            }
        }

        // ---- causal mask (blocks touching the diagonal for this warp) ----
        int ig0 = q0 + wid * 16 + g;
        int ig1 = ig0 + 8;
        if (kb * 64 + 63 > q0 + wid * 16) {
            #pragma unroll
            for (int nj = 0; nj < 8; nj++) {
                int c0 = kb * 64 + nj * 8 + t * 2;
                if (c0     > ig0) sacc[nj][0] = -1e30f;
                if (c0 + 1 > ig0) sacc[nj][1] = -1e30f;
                if (c0     > ig1) sacc[nj][2] = -1e30f;
                if (c0 + 1 > ig1) sacc[nj][3] = -1e30f;
            }
        }

        // ---- online softmax ----
        float rmax0 = -1e30f, rmax1 = -1e30f;
        #pragma unroll
        for (int nj = 0; nj < 8; nj++) {
            rmax0 = fmaxf(rmax0, fmaxf(sacc[nj][0], sacc[nj][1]));
            rmax1 = fmaxf(rmax1, fmaxf(sacc[nj][2], sacc[nj][3]));
        }
        rmax0 = fmaxf(rmax0, __shfl_xor_sync(0xffffffffu, rmax0, 1));
        rmax0 = fmaxf(rmax0, __shfl_xor_sync(0xffffffffu, rmax0, 2));
        rmax1 = fmaxf(rmax1, __shfl_xor_sync(0xffffffffu, rmax1, 1));
        rmax1 = fmaxf(rmax1, __shfl_xor_sync(0xffffffffu, rmax1, 2));
        float mn0 = fmaxf(m0, rmax0), mn1 = fmaxf(m1, rmax1);
        float alpha0 = __expf(m0 - mn0), alpha1 = __expf(m1 - mn1);
        float rs0 = 0.f, rs1 = 0.f;
        #pragma unroll
        for (int nj = 0; nj < 8; nj++) {
            float p0 = __expf(sacc[nj][0] - mn0);
            float p1 = __expf(sacc[nj][1] - mn0);
            float p2 = __expf(sacc[nj][2] - mn1);
            float p3 = __expf(sacc[nj][3] - mn1);
            sacc[nj][0] = p0; sacc[nj][1] = p1; sacc[nj][2] = p2; sacc[nj][3] = p3;
            rs0 += p0 + p1;
            rs1 += p2 + p3;
        }
        rs0 += __shfl_xor_sync(0xffffffffu, rs0, 1);
        rs0 += __shfl_xor_sync(0xffffffffu, rs0, 2);
        rs1 += __shfl_xor_sync(0xffffffffu, rs1, 1);
        rs1 += __shfl_xor_sync(0xffffffffu, rs1, 2);
        l0 = l0 * alpha0 + rs0;
        l1 = l1 * alpha1 + rs1;
        m0 = mn0; m1 = mn1;

        #pragma unroll
        for (int dj = 0; dj < 16; dj++) {
            po[dj][0] *= alpha0; po[dj][1] *= alpha0;
            po[dj][2] *= alpha1; po[dj][3] *= alpha1;
        }

        // ---- O += (Ph+Pl) @ V ----
        #pragma unroll
        for (int kc2 = 0; kc2 < 4; kc2++) {
            uint32_t ph[4], pl[4];
            {
                float r0, r1;
                ph[0] = pack_hi_h(sacc[2 * kc2][0],     sacc[2 * kc2][1],     r0, r1);
                pl[0] = pack_h2(r0, r1);
                ph[1] = pack_hi_h(sacc[2 * kc2][2],     sacc[2 * kc2][3],     r0, r1);
                pl[1] = pack_h2(r0, r1);
                ph[2] = pack_hi_h(sacc[2 * kc2 + 1][0], sacc[2 * kc2 + 1][1], r0, r1);
                pl[2] = pack_h2(r0, r1);
                ph[3] = pack_hi_h(sacc[2 * kc2 + 1][2], sacc[2 * kc2 + 1][3], r0, r1);
                pl[3] = pack_h2(r0, r1);
            }
            #pragma unroll
            for (int ds = 0; ds < 8; ds++) {
                uint32_t vh[4];
                uint32_t aoff = ((kc2 * 16 + vrow) * AT_ROWP + ds * 16 + vcolx) * 2;
                ldsm4t(vh, aV + aoff);
                mma16816(po[2 * ds],     ph, &vh[0]);
                mma16816(po[2 * ds],     pl, &vh[0]);
                mma16816(po[2 * ds + 1], ph, &vh[2]);
                mma16816(po[2 * ds + 1], pl, &vh[2]);
            }
        }
    }

    // ---- epilogue: normalize, split hi/lo fp16, store ----
    float inv0 = 1.f / l0, inv1 = 1.f / l1;
    size_t tok0 = (size_t)(b * SEQT + q0 + wid * 16 + g);
    size_t tok1 = tok0 + 8;
    #pragma unroll
    for (int dj = 0; dj < 16; dj++) {
        int col = h * HD + dj * 8 + t * 2;
        float v0 = po[dj][0] * inv0, v1 = po[dj][1] * inv0;
        float v2 = po[dj][2] * inv1, v3 = po[dj][3] * inv1;
        float r0, r1, r2, r3;
        uint32_t h01 = pack_hi_h(v0, v1, r0, r1);
        uint32_t h23 = pack_hi_h(v2, v3, r2, r3);
        *(uint32_t*)(Oh + tok0 * DIM + col) = h01;
        *(uint32_t*)(Oh + tok1 * DIM + col) = h23;
        *(uint32_t*)(Ol + tok0 * DIM + col) = pack_h2(r0, r1);
        *(uint32_t*)(Ol + tok1 * DIM + col) = pack_h2(r2, r3);
    }
}

// ---------------------------------------------------------------------------
extern "C" void kernel_launch(void* const* d_in, const int* in_sizes, int n_in,
                              void* d_out, int out_size) {
    const float* enc = (const float*)d_in[0];
    const float* dec = (const float*)d_in[1];
    const float* Wkv = (const float*)d_in[2];
    const float* bkv = (const float*)d_in[3];
    const float* Wq  = (const float*)d_in[4];
    const float* bq  = (const float*)d_in[5];
    const float* Wo  = (const float*)d_in[6];
    const float* bo  = (const float*)d_in[7];
    float* out = (float*)d_out;

    __half *eh, *el, *dh, *dl, *kv, *qh, *ql, *aoh, *aol, *wkv, *wq, *wo;
    cudaGetSymbolAddress((void**)&eh,  g_enc_h);  cudaGetSymbolAddress((void**)&el,  g_enc_l);
    cudaGetSymbolAddress((void**)&dh,  g_dec_h);  cudaGetSymbolAddress((void**)&dl,  g_dec_l);
    cudaGetSymbolAddress((void**)&kv,  g_kv);
    cudaGetSymbolAddress((void**)&qh,  g_q_h);    cudaGetSymbolAddress((void**)&ql,  g_q_l);
    cudaGetSymbolAddress((void**)&aoh, g_ao_h);   cudaGetSymbolAddress((void**)&aol, g_ao_l);
    cudaGetSymbolAddress((void**)&wkv, g_wkv);
    cudaGetSymbolAddress((void**)&wq,  g_wq);
    cudaGetSymbolAddress((void**)&wo,  g_wo);

    cudaFuncSetAttribute(gemm_tc, cudaFuncAttributeMaxDynamicSharedMemorySize, GT_SMEM);
    cudaFuncSetAttribute(attn_mma, cudaFuncAttributeMaxDynamicSharedMemorySize, AT_SMEM);

    int n4_act = (M_TOK * DIM) / 4;
    const float qscale = 0.08838834764831845f;   // 1/sqrt(128)

    split_kernel<<<(n4_act + 255) / 256, 256>>>(enc, eh, el, n4_act);
    split_kernel<<<(n4_act + 255) / 256, 256>>>(dec, dh, dl, n4_act);
    roundT_kernel<<<dim3(TWO_DIM / 32, DIM / 32), 256>>>(Wkv, wkv, DIM, TWO_DIM);
    roundT_kernel<<<dim3(DIM / 32,     DIM / 32), 256>>>(Wq,  wq,  DIM, DIM);
    roundT_kernel<<<dim3(DIM / 32,     DIM / 32), 256>>>(Wo,  wo,  DIM, DIM);

    // KV projection -> single fp16 (mode 2)
    gemm_tc<<<dim3(TWO_DIM / 128, M_TOK / 128), 256, GT_SMEM>>>(
        eh, el, wkv, bkv, 1.0f, nullptr, kv, nullptr, 2, M_TOK, TWO_DIM, DIM);
    // Q projection -> fp16 hi/lo, pre-scaled (mode 1)
    gemm_tc<<<dim3(DIM / 128, M_TOK / 128), 256, GT_SMEM>>>(
        dh, dl, wq, bq, qscale, nullptr, qh, ql, 1, M_TOK, DIM, DIM);

    // attention -> fp16 hi/lo
    attn_mma<<<dim3(SEQT / 128, NH, BATCH), 256, AT_SMEM>>>(qh, ql, kv, aoh, aol);

    // O projection -> fp32 out (mode 0)
    gemm_tc<<<dim3(DIM / 128, M_TOK / 128), 256, GT_SMEM>>>(
        aoh, aol, wo, bo, 1.0f, out, nullptr, nullptr, 0, M_TOK, DIM, DIM);
}